// round 7
// baseline (speedup 1.0000x reference)
#include <cuda_runtime.h>
#include <cuda_bf16.h>
#include <cstdint>

// ---------------- problem constants ----------------
#define TT   128      // seq len
#define BB   64       // batch
#define HH   512      // hidden
#define VV   10000    // vocab

// split-bf16: X = Xhi + Xlo (bf16 each); products hi*hi + lo*hi + hi*lo
#define KSTORE 1024
#define TM     128
#define TN     256
#define TK     32
#define KTILES 48
#define STAGES 4
#define MTILES (TT * BB / TM)   // 64
#define NTILES 40               // 40 * 256 = 10240
#define VPAD   (NTILES * TN)

#define A_ROW_B   80
#define A_ST_B    (TM * A_ROW_B)
#define B_ST_B    (TN * A_ROW_B)
#define STAGE_B   (A_ST_B + B_ST_B)

#define OUT_STATE_OFF 81920000u
#define OUT_CELL_OFF  81952768u

// ---------------- device scratch ----------------
// g_A2: 129 slots x 64 rows x 1024 bf16.  slot s row b = split-bf16 of h_{s-1}[b]
// (slot 0 = state0). GEMM A row for (t,b) = 64 + t*64 + b.
__device__ __align__(16) __nv_bfloat16 g_A2[(size_t)(TT + 1) * BB * KSTORE];
__device__ __align__(16) __nv_bfloat16 g_B2T[(size_t)VPAD * KSTORE];     // 20 MB
__device__ __align__(16) __nv_bfloat16 g_WB[(size_t)2048 * KSTORE];      // 4 MB
__device__ unsigned g_cnt = 0;
__device__ unsigned g_gen = 0;

__device__ __forceinline__ float sigmoidf_(float x) { return 1.0f / (1.0f + expf(-x)); }

__device__ __forceinline__ uint32_t smem_u32(const void* p) {
    uint32_t a;
    asm("{ .reg .u64 t; cvta.to.shared.u64 t, %1; cvt.u32.u64 %0, t; }" : "=r"(a) : "l"(p));
    return a;
}
__device__ __forceinline__ void cp_async16(uint32_t dst, const void* src) {
    asm volatile("cp.async.cg.shared.global [%0], [%1], 16;" :: "r"(dst), "l"(src));
}
__device__ __forceinline__ void ldsm_x4(uint32_t* r, uint32_t addr) {
    asm volatile("ldmatrix.sync.aligned.m8n8.x4.shared.b16 {%0,%1,%2,%3}, [%4];"
                 : "=r"(r[0]), "=r"(r[1]), "=r"(r[2]), "=r"(r[3]) : "r"(addr));
}
__device__ __forceinline__ void mma16816(float* c, const uint32_t* a, uint32_t b0, uint32_t b1) {
    asm volatile("mma.sync.aligned.m16n8k16.row.col.f32.bf16.bf16.f32 "
                 "{%0,%1,%2,%3}, {%4,%5,%6,%7}, {%8,%9}, {%0,%1,%2,%3};"
                 : "+f"(c[0]), "+f"(c[1]), "+f"(c[2]), "+f"(c[3])
                 : "r"(a[0]), "r"(a[1]), "r"(a[2]), "r"(a[3]), "r"(b0), "r"(b1));
}

// ---------------- prep: W_h* -> g_WB [2048 rows][1024] bf16 hi|lo ------------
// row gr for (gate g, unit j): gr = (j>>3)*32 + g*8 + (j&7)   (CTA-local grouping)
__global__ void __launch_bounds__(256)
build_whb(const float* __restrict__ Wi, const float* __restrict__ Wf,
          const float* __restrict__ Wo, const float* __restrict__ Wc) {
    __shared__ float tile[32][33];
    const int kt = blockIdx.x, jt = blockIdx.y, g = blockIdx.z;
    const int tid = threadIdx.x;
    const float* W = (g == 0) ? Wi : (g == 1) ? Wf : (g == 2) ? Wo : Wc;
    for (int i = tid; i < 1024; i += 256) {
        int kk = i >> 5, jj = i & 31;
        tile[kk][jj] = W[(kt * 32 + kk) * HH + jt * 32 + jj];
    }
    __syncthreads();
    for (int i = tid; i < 1024; i += 256) {
        int jj = i >> 5, kk = i & 31;
        float w = tile[kk][jj];
        int j  = jt * 32 + jj;
        int gr = (j >> 3) * 32 + g * 8 + (j & 7);
        __nv_bfloat16 hi = __float2bfloat16(w);
        g_WB[(size_t)gr * KSTORE + kt * 32 + kk] = hi;
        g_WB[(size_t)gr * KSTORE + 512 + kt * 32 + kk] =
            __float2bfloat16(w - __bfloat162float(hi));
    }
}

// ---------------- prep: W_hq -> B^T bf16 [VPAD][1024] = [hi|lo] --------------
__global__ void __launch_bounds__(256)
build_b2t(const float* __restrict__ Whq) {
    extern __shared__ float stile[];          // [64][257]
    const int kc = blockIdx.x;
    const int nt = blockIdx.y;
    const int tid = threadIdx.x;
    for (int idx = tid; idx < 64 * 256; idx += 256) {
        int kk = idx >> 8, nn = idx & 255;
        int n = nt * 256 + nn;
        stile[kk * 257 + nn] = (n < VV) ? Whq[(kc * 64 + kk) * VV + n] : 0.0f;
    }
    __syncthreads();
    for (int c = tid; c < 256 * 8; c += 256) {
        int row = c >> 3, ch = c & 7;
        __nv_bfloat16 hv[8], lv[8];
        #pragma unroll
        for (int i = 0; i < 8; i++) {
            float w = stile[(ch * 8 + i) * 257 + row];
            __nv_bfloat16 hi = __float2bfloat16(w);
            hv[i] = hi;
            lv[i] = __float2bfloat16(w - __bfloat162float(hi));
        }
        size_t base = (size_t)(nt * 256 + row) * KSTORE + kc * 64 + ch * 8;
        *reinterpret_cast<int4*>(&g_B2T[base])       = *reinterpret_cast<int4*>(hv);
        *reinterpret_cast<int4*>(&g_B2T[base + 512]) = *reinterpret_cast<int4*>(lv);
    }
}

// ---------------- prep: state0 -> g_A2 slot 0 --------------------------------
__global__ void build_h0(const float* __restrict__ state0) {
    int idx = blockIdx.x * blockDim.x + threadIdx.x;   // 8-float chunk
    if (idx >= BB * 64) return;
    int m = idx >> 6, k = (idx & 63) * 8;
    const float* src = state0 + (size_t)m * HH + k;
    float4 f0 = *reinterpret_cast<const float4*>(src);
    float4 f1 = *reinterpret_cast<const float4*>(src + 4);
    float fv[8] = {f0.x, f0.y, f0.z, f0.w, f1.x, f1.y, f1.z, f1.w};
    __nv_bfloat16 hv[8], lv[8];
    #pragma unroll
    for (int i = 0; i < 8; i++) {
        __nv_bfloat16 hi = __float2bfloat16(fv[i]);
        hv[i] = hi;
        lv[i] = __float2bfloat16(fv[i] - __bfloat162float(hi));
    }
    *reinterpret_cast<int4*>(&g_A2[(size_t)m * KSTORE + k])       = *reinterpret_cast<int4*>(hv);
    *reinterpret_cast<int4*>(&g_A2[(size_t)m * KSTORE + 512 + k]) = *reinterpret_cast<int4*>(lv);
}

// ---------------- tensor-core persistent LSTM recurrence ---------------------
// 64 CTAs, 256 threads (8 warps = 4 m-groups x 2 n-groups).
// CTA c owns units [8c, 8c+8) x 4 gates = 32 N-cols; weights pinned in SMEM.
// Per step: cp.async h (bf16 hi|lo, 128KB) -> smem, 3-product mma, fragment
// exchange via smem, elementwise, write h (hi|lo) directly into g_A2 slot t+1.
#define HROW_B 2064   // 1024 bf16 + 16B pad (ldsm conflict-free: 2064 % 128 = 16)
#define SM_H   0
#define SM_W   (64 * HROW_B)                 // 132096
#define SM_P   (SM_W + 32 * HROW_B)          // 198144
#define SM_C   (SM_P + 64 * 32 * 4)          // 206336
#define SM_TOT (SM_C + 512 * 4)              // 208384

__global__ void __launch_bounds__(256, 1)
lstm_tc(const int* __restrict__ x, const float* __restrict__ cell0,
        const float* __restrict__ Wxi, const float* __restrict__ Wxf,
        const float* __restrict__ Wxo, const float* __restrict__ Wxc,
        const float* __restrict__ bi,  const float* __restrict__ bf_,
        const float* __restrict__ bo,  const float* __restrict__ bc,
        float* __restrict__ out) {
    extern __shared__ __align__(128) char sm[];
    const uint32_t hbase = smem_u32(sm);
    const uint32_t wbase = hbase + SM_W;
    float* pbuf  = reinterpret_cast<float*>(sm + SM_P);
    float* cellb = reinterpret_cast<float*>(sm + SM_C);

    const int tid = threadIdx.x;
    const int wid = tid >> 5;
    const int lid = tid & 31;
    const int cta = blockIdx.x;
    const int j0  = cta * 8;
    const int mg  = wid >> 1;          // m-group: rows [mg*16, +16)
    const int ng  = wid & 1;           // n-group: cols [ng*16, +16)
    const int lr  = lid & 15;
    const int lc  = (lid >> 4) * 16;

    // elementwise role: b = tid>>2, units u0, u0+1
    const int eb = tid >> 2;
    const int u0 = (tid & 3) * 2;

    unsigned genBase = 0;
    if (tid == 0) genBase = *(volatile unsigned*)&g_gen;

    // pin weights in smem (32 rows x 2048B)
    {
        const char* src = (const char*)(g_WB + (size_t)(cta * 32) * KSTORE);
        for (int c = tid; c < 4096; c += 256) {
            int r = c >> 7, cc = c & 127;
            cp_async16(wbase + r * HROW_B + cc * 16, src + (size_t)r * 2048 + cc * 16);
        }
        asm volatile("cp.async.commit_group;" ::: "memory");
    }
    // cell -> smem
    for (int i = tid; i < 512; i += 256)
        cellb[i] = cell0[(size_t)(i >> 3) * HH + j0 + (i & 7)];

    // per-thread constants for elementwise
    const float2 bi2 = *reinterpret_cast<const float2*>(bi  + j0 + u0);
    const float2 bf2 = *reinterpret_cast<const float2*>(bf_ + j0 + u0);
    const float2 bo2 = *reinterpret_cast<const float2*>(bo  + j0 + u0);
    const float2 bc2 = *reinterpret_cast<const float2*>(bc  + j0 + u0);

    asm volatile("cp.async.wait_group 0;" ::: "memory");
    __syncthreads();

    for (int t = 0; t < TT; t++) {
        // ---- stage h (slot t) into smem ----
        const char* Asrc = (const char*)(g_A2 + (size_t)t * BB * KSTORE);
        for (int c = tid; c < 8192; c += 256) {
            int r = c >> 7, cc = c & 127;
            cp_async16(hbase + r * HROW_B + cc * 16, Asrc + (size_t)r * 2048 + cc * 16);
        }
        asm volatile("cp.async.commit_group;" ::: "memory");
        asm volatile("cp.async.wait_group 0;" ::: "memory");
        __syncthreads();

        // ---- 3-product split-bf16 mma: fused k-loop, shared fragments ----
        float acc0[4] = {0.f, 0.f, 0.f, 0.f};
        float acc1[4] = {0.f, 0.f, 0.f, 0.f};
        const uint32_t ha = hbase + (mg * 16 + lr) * HROW_B + lc;
        const uint32_t wa = wbase + (ng * 16 + lr) * HROW_B + lc;
        #pragma unroll 4
        for (int kt = 0; kt < 32; kt++) {
            uint32_t ahi[4], alo[4], bhi[4], blo[4];
            ldsm_x4(ahi, ha + kt * 32);
            ldsm_x4(alo, ha + 1024 + kt * 32);
            ldsm_x4(bhi, wa + kt * 32);
            ldsm_x4(blo, wa + 1024 + kt * 32);
            mma16816(acc0, ahi, bhi[0], bhi[2]);
            mma16816(acc1, ahi, bhi[1], bhi[3]);
            mma16816(acc0, alo, bhi[0], bhi[2]);
            mma16816(acc1, alo, bhi[1], bhi[3]);
            mma16816(acc0, ahi, blo[0], blo[2]);
            mma16816(acc1, ahi, blo[1], blo[3]);
        }

        // ---- exchange fragments via smem ----
        {
            const int qr = lid >> 2;
            const int qc = (lid & 3) * 2;
            int row = mg * 16 + qr;
            int col = ng * 16 + qc;
            pbuf[row * 32 + col]           = acc0[0];
            pbuf[row * 32 + col + 1]       = acc0[1];
            pbuf[(row + 8) * 32 + col]     = acc0[2];
            pbuf[(row + 8) * 32 + col + 1] = acc0[3];
            pbuf[row * 32 + col + 8]       = acc1[0];
            pbuf[row * 32 + col + 9]       = acc1[1];
            pbuf[(row + 8) * 32 + col + 8] = acc1[2];
            pbuf[(row + 8) * 32 + col + 9] = acc1[3];
        }
        __syncthreads();

        // ---- elementwise: gates, c/h update, write split-bf16 h ----
        {
            int tok = x[eb * TT + t];
            const size_t wxo_ = (size_t)tok * HH + j0 + u0;
            float2 wxi2 = *reinterpret_cast<const float2*>(Wxi + wxo_);
            float2 wxf2 = *reinterpret_cast<const float2*>(Wxf + wxo_);
            float2 wxo2 = *reinterpret_cast<const float2*>(Wxo + wxo_);
            float2 wxc2 = *reinterpret_cast<const float2*>(Wxc + wxo_);
            const float* pr = pbuf + eb * 32;

            float i0 = sigmoidf_(pr[u0]          + bi2.x + wxi2.x);
            float i1 = sigmoidf_(pr[u0 + 1]      + bi2.y + wxi2.y);
            float f0 = sigmoidf_(pr[8 + u0]      + bf2.x + wxf2.x);
            float f1 = sigmoidf_(pr[8 + u0 + 1]  + bf2.y + wxf2.y);
            float o0 = sigmoidf_(pr[16 + u0]     + bo2.x + wxo2.x);
            float o1 = sigmoidf_(pr[16 + u0 + 1] + bo2.y + wxo2.y);
            float g0 = tanhf    (pr[24 + u0]     + bc2.x + wxc2.x);
            float g1 = tanhf    (pr[24 + u0 + 1] + bc2.y + wxc2.y);

            float c0 = cellb[eb * 8 + u0];
            float c1 = cellb[eb * 8 + u0 + 1];
            float cn0 = fmaf(f0, c0, i0 * g0);
            float cn1 = fmaf(f1, c1, i1 * g1);
            cellb[eb * 8 + u0]     = cn0;
            cellb[eb * 8 + u0 + 1] = cn1;
            float hn0 = o0 * tanhf(cn0);
            float hn1 = o1 * tanhf(cn1);

            __nv_bfloat16 h0 = __float2bfloat16(hn0);
            __nv_bfloat16 h1 = __float2bfloat16(hn1);
            __nv_bfloat16 l0 = __float2bfloat16(hn0 - __bfloat162float(h0));
            __nv_bfloat16 l1 = __float2bfloat16(hn1 - __bfloat162float(h1));
            uint32_t hib = (uint32_t)__bfloat16_as_ushort(h0) |
                           ((uint32_t)__bfloat16_as_ushort(h1) << 16);
            uint32_t lob = (uint32_t)__bfloat16_as_ushort(l0) |
                           ((uint32_t)__bfloat16_as_ushort(l1) << 16);
            char* dst = (char*)(g_A2 + (size_t)(t + 1) * BB * KSTORE) + (size_t)eb * 2048;
            *reinterpret_cast<uint32_t*>(dst + (j0 + u0) * 2)        = hib;
            *reinterpret_cast<uint32_t*>(dst + 1024 + (j0 + u0) * 2) = lob;
            if (t == TT - 1) {
                float2 hv = {hn0, hn1};
                *reinterpret_cast<float2*>(out + OUT_STATE_OFF + (size_t)eb * HH + j0 + u0) = hv;
            }
        }
        __threadfence();
        __syncthreads();

        // ---- software grid barrier (64 CTAs, single wave) ----
        if (t < TT - 1) {
            if (tid == 0) {
                unsigned arr = atomicAdd(&g_cnt, 1u);
                if (arr == gridDim.x - 1) {
                    atomicExch(&g_cnt, 0u);
                    __threadfence();
                    atomicAdd(&g_gen, 1u);
                } else {
                    unsigned target = (unsigned)(t + 1);
                    while ((*(volatile unsigned*)&g_gen) - genBase < target)
                        __nanosleep(40);
                }
                __threadfence();
            }
            __syncthreads();
        }
    }

    // final cell -> out
    for (int i = tid; i < 512; i += 256)
        out[OUT_CELL_OFF + (size_t)(i >> 3) * HH + j0 + (i & 7)] = cellb[i];
}

// ---------------- mma.sync output GEMM (A rows offset by 64) ------------------
__global__ void __launch_bounds__(256, 1)
gemm_mma(const float* __restrict__ bq, float* __restrict__ out) {
    extern __shared__ __align__(128) char dsm[];
    const uint32_t sbase = smem_u32(dsm);
    const int tid = threadIdx.x;
    const int wid = tid >> 5;
    const int lid = tid & 31;
    const int nt  = blockIdx.x;
    const int mt  = blockIdx.y;
    const int m0  = mt * TM;
    const int n0  = nt * TN;
    const int wm  = (wid >> 2) * 64;
    const int wn  = (wid & 3) * 64;

    const __nv_bfloat16* gA = g_A2  + (size_t)(BB + m0) * KSTORE;  // skip slot 0
    const __nv_bfloat16* gB = g_B2T + (size_t)n0 * KSTORE;

    auto a_off = [](int kt) { return ((kt < 32) ? kt : kt - 32) * TK; };
    auto b_off = [](int kt) { return ((kt < 16) ? kt : kt - 16) * TK; };

    float acc[4][8][4];
    #pragma unroll
    for (int i = 0; i < 4; i++)
        #pragma unroll
        for (int j = 0; j < 8; j++)
            #pragma unroll
            for (int q = 0; q < 4; q++) acc[i][j][q] = 0.0f;

    auto load_stage = [&](int kt, int s) {
        uint32_t dA = sbase + s * STAGE_B;
        uint32_t dB = dA + A_ST_B;
        int ao = a_off(kt), bo = b_off(kt);
        #pragma unroll
        for (int c = 0; c < 2; c++) {
            int ch = (c * 256 + tid);
            int row = ch >> 2, cc = ch & 3;
            cp_async16(dA + row * A_ROW_B + cc * 16,
                       gA + (size_t)row * KSTORE + ao + cc * 8);
        }
        #pragma unroll
        for (int c = 0; c < 4; c++) {
            int ch = (c * 256 + tid);
            int row = ch >> 2, cc = ch & 3;
            cp_async16(dB + row * A_ROW_B + cc * 16,
                       gB + (size_t)row * KSTORE + bo + cc * 8);
        }
        asm volatile("cp.async.commit_group;" ::: "memory");
    };

    #pragma unroll
    for (int s = 0; s < STAGES - 1; s++) load_stage(s, s);

    const int lr = lid & 15;
    const int lc = (lid >> 4) * 16;

    for (int t = 0; t < KTILES; t++) {
        const int s = t & (STAGES - 1);
        if (t <= KTILES - 3)      asm volatile("cp.async.wait_group 2;" ::: "memory");
        else if (t == KTILES - 2) asm volatile("cp.async.wait_group 1;" ::: "memory");
        else                      asm volatile("cp.async.wait_group 0;" ::: "memory");
        __syncthreads();

        const int tn = t + STAGES - 1;
        if (tn < KTILES) load_stage(tn, tn & (STAGES - 1));

        const uint32_t Ab = sbase + s * STAGE_B;
        const uint32_t Bb = Ab + A_ST_B;
        #pragma unroll
        for (int ks2 = 0; ks2 < 2; ks2++) {
            uint32_t af[4][4], bf[4][4];
            #pragma unroll
            for (int i = 0; i < 4; i++)
                ldsm_x4(af[i], Ab + (wm + i * 16 + lr) * A_ROW_B + ks2 * 32 + lc);
            #pragma unroll
            for (int j = 0; j < 4; j++)
                ldsm_x4(bf[j], Bb + (wn + j * 16 + lr) * A_ROW_B + ks2 * 32 + lc);
            #pragma unroll
            for (int i = 0; i < 4; i++)
                #pragma unroll
                for (int j = 0; j < 4; j++) {
                    mma16816(acc[i][2 * j],     af[i], bf[j][0], bf[j][2]);
                    mma16816(acc[i][2 * j + 1], af[i], bf[j][1], bf[j][3]);
                }
        }
        __syncthreads();
    }

    const int qr = lid >> 2;
    const int qc = (lid & 3) * 2;
    float2 bias2[8];
    #pragma unroll
    for (int j = 0; j < 8; j++) {
        int n = n0 + wn + j * 8 + qc;
        bias2[j].x = (n < VV)     ? bq[n]     : 0.0f;
        bias2[j].y = (n + 1 < VV) ? bq[n + 1] : 0.0f;
    }
    #pragma unroll
    for (int i = 0; i < 4; i++) {
        int mrow = m0 + wm + i * 16 + qr;
        #pragma unroll
        for (int j = 0; j < 8; j++) {
            int n = n0 + wn + j * 8 + qc;
            if (n < VV) {
                float2 v0 = {acc[i][j][0] + bias2[j].x, acc[i][j][1] + bias2[j].y};
                float2 v1 = {acc[i][j][2] + bias2[j].x, acc[i][j][3] + bias2[j].y};
                *reinterpret_cast<float2*>(out + (size_t)mrow * VV + n) = v0;
                *reinterpret_cast<float2*>(out + (size_t)(mrow + 8) * VV + n) = v1;
            }
        }
    }
}

// ---------------- launch ----------------
extern "C" void kernel_launch(void* const* d_in, const int* in_sizes, int n_in,
                              void* d_out, int out_size) {
    const int*   x     = (const int*)  d_in[0];
    const float* state = (const float*)d_in[1];
    const float* cell  = (const float*)d_in[2];
    const float* W_xi  = (const float*)d_in[3];
    const float* W_hi  = (const float*)d_in[4];
    const float* b_i   = (const float*)d_in[5];
    const float* W_xf  = (const float*)d_in[6];
    const float* W_hf  = (const float*)d_in[7];
    const float* b_f   = (const float*)d_in[8];
    const float* W_xo  = (const float*)d_in[9];
    const float* W_ho  = (const float*)d_in[10];
    const float* b_o   = (const float*)d_in[11];
    const float* W_xc  = (const float*)d_in[12];
    const float* W_hc  = (const float*)d_in[13];
    const float* b_c   = (const float*)d_in[14];
    const float* W_hq  = (const float*)d_in[15];
    const float* b_q   = (const float*)d_in[16];
    float* out = (float*)d_out;

    cudaFuncSetAttribute(lstm_tc, cudaFuncAttributeMaxDynamicSharedMemorySize, SM_TOT);
    size_t b2t_smem = 64 * 257 * sizeof(float);
    cudaFuncSetAttribute(build_b2t, cudaFuncAttributeMaxDynamicSharedMemorySize,
                         (int)b2t_smem);
    size_t gemm_smem = (size_t)STAGES * STAGE_B;
    cudaFuncSetAttribute(gemm_mma, cudaFuncAttributeMaxDynamicSharedMemorySize,
                         (int)gemm_smem);

    build_whb<<<dim3(16, 16, 4), 256>>>(W_hi, W_hf, W_ho, W_hc);
    build_b2t<<<dim3(8, NTILES), 256, b2t_smem>>>(W_hq);
    build_h0<<<16, 256>>>(state);
    lstm_tc<<<64, 256, SM_TOT>>>(x, cell,
                                 W_xi, W_xf, W_xo, W_xc,
                                 b_i, b_f, b_o, b_c, out);
    gemm_mma<<<dim3(NTILES, MTILES), 256, gemm_smem>>>(b_q, out);
}

// round 8
// speedup vs baseline: 1.0870x; 1.0870x over previous
#include <cuda_runtime.h>
#include <cuda_bf16.h>
#include <cstdint>

// ---------------- problem constants ----------------
#define TT   128      // seq len
#define BB   64       // batch
#define HH   512      // hidden
#define VV   10000    // vocab

// split-bf16: X = Xhi + Xlo; products hi*hi + lo*hi + hi*lo  (K' = 1536 logical)
#define KSTORE 1024
#define TK     32
#define KTILES 48

// output GEMM tiling: 128x128 CTA tiles, 2 CTAs/SM
#define TM2    128
#define TN2    128
#define MTILES 64                // 8192 / 128
#define NTILES 80                // 80*128 = 10240
#define VPAD   (NTILES * TN2)
#define STAGES 4
#define G_ROW_B  80              // 64B data + 16B pad
#define G_AST_B  (TM2 * G_ROW_B) // 10240
#define G_BST_B  (TN2 * G_ROW_B) // 10240
#define G_STG_B  (G_AST_B + G_BST_B) // 20480

#define OUT_STATE_OFF 81920000u
#define OUT_CELL_OFF  81952768u

// ---------------- device scratch ----------------
// g_A2: 129 slots x 64 rows x 1024 bf16 (slot s = split-bf16 of h_{s-1}; slot0 = state0)
__device__ __align__(16) __nv_bfloat16 g_A2[(size_t)(TT + 1) * BB * KSTORE];
__device__ __align__(16) __nv_bfloat16 g_B2T[(size_t)VPAD * KSTORE];     // 20 MB
__device__ __align__(16) __nv_bfloat16 g_WB[(size_t)2048 * KSTORE];      // 4 MB
__device__ __align__(16) float g_XQ[(size_t)TT * BB * 2048];             // 64 MB
__device__ unsigned g_cnt = 0;
__device__ unsigned g_gen = 0;

__device__ __forceinline__ float sigmoidf_(float x) { return 1.0f / (1.0f + expf(-x)); }

__device__ __forceinline__ uint32_t smem_u32(const void* p) {
    uint32_t a;
    asm("{ .reg .u64 t; cvta.to.shared.u64 t, %1; cvt.u32.u64 %0, t; }" : "=r"(a) : "l"(p));
    return a;
}
__device__ __forceinline__ void cp_async16(uint32_t dst, const void* src) {
    asm volatile("cp.async.cg.shared.global [%0], [%1], 16;" :: "r"(dst), "l"(src));
}
__device__ __forceinline__ void ldsm_x4(uint32_t* r, uint32_t addr) {
    asm volatile("ldmatrix.sync.aligned.m8n8.x4.shared.b16 {%0,%1,%2,%3}, [%4];"
                 : "=r"(r[0]), "=r"(r[1]), "=r"(r[2]), "=r"(r[3]) : "r"(addr));
}
__device__ __forceinline__ void mma16816(float* c, const uint32_t* a, uint32_t b0, uint32_t b1) {
    asm volatile("mma.sync.aligned.m16n8k16.row.col.f32.bf16.bf16.f32 "
                 "{%0,%1,%2,%3}, {%4,%5,%6,%7}, {%8,%9}, {%0,%1,%2,%3};"
                 : "+f"(c[0]), "+f"(c[1]), "+f"(c[2]), "+f"(c[3])
                 : "r"(a[0]), "r"(a[1]), "r"(a[2]), "r"(a[3]), "r"(b0), "r"(b1));
}

// ---------------- prep: W_h* -> g_WB [2048 rows][1024] bf16 hi|lo ------------
// row for (gate g, unit j): gr = (j>>3)*32 + g*8 + (j&7)
__global__ void __launch_bounds__(256)
build_whb(const float* __restrict__ Wi, const float* __restrict__ Wf,
          const float* __restrict__ Wo, const float* __restrict__ Wc) {
    __shared__ float tile[32][33];
    const int kt = blockIdx.x, jt = blockIdx.y, g = blockIdx.z;
    const int tid = threadIdx.x;
    const float* W = (g == 0) ? Wi : (g == 1) ? Wf : (g == 2) ? Wo : Wc;
    for (int i = tid; i < 1024; i += 256) {
        int kk = i >> 5, jj = i & 31;
        tile[kk][jj] = W[(kt * 32 + kk) * HH + jt * 32 + jj];
    }
    __syncthreads();
    for (int i = tid; i < 1024; i += 256) {
        int jj = i >> 5, kk = i & 31;
        float w = tile[kk][jj];
        int j  = jt * 32 + jj;
        int gr = (j >> 3) * 32 + g * 8 + (j & 7);
        __nv_bfloat16 hi = __float2bfloat16(w);
        g_WB[(size_t)gr * KSTORE + kt * 32 + kk] = hi;
        g_WB[(size_t)gr * KSTORE + 512 + kt * 32 + kk] =
            __float2bfloat16(w - __bfloat162float(hi));
    }
}

// ---------------- prep: W_hq -> B^T bf16 [VPAD][1024] = [hi|lo] --------------
__global__ void __launch_bounds__(256)
build_b2t(const float* __restrict__ Whq) {
    extern __shared__ float stile[];          // [64][257]
    const int kc = blockIdx.x;
    const int nt = blockIdx.y;
    const int tid = threadIdx.x;
    for (int idx = tid; idx < 64 * 256; idx += 256) {
        int kk = idx >> 8, nn = idx & 255;
        int n = nt * 256 + nn;
        stile[kk * 257 + nn] = (n < VV) ? Whq[(kc * 64 + kk) * VV + n] : 0.0f;
    }
    __syncthreads();
    for (int c = tid; c < 256 * 8; c += 256) {
        int row = c >> 3, ch = c & 7;
        __nv_bfloat16 hv[8], lv[8];
        #pragma unroll
        for (int i = 0; i < 8; i++) {
            float w = stile[(ch * 8 + i) * 257 + row];
            __nv_bfloat16 hi = __float2bfloat16(w);
            hv[i] = hi;
            lv[i] = __float2bfloat16(w - __bfloat162float(hi));
        }
        size_t base = (size_t)(nt * 256 + row) * KSTORE + kc * 64 + ch * 8;
        *reinterpret_cast<int4*>(&g_B2T[base])       = *reinterpret_cast<int4*>(hv);
        *reinterpret_cast<int4*>(&g_B2T[base + 512]) = *reinterpret_cast<int4*>(lv);
    }
}

// ---------------- prep: state0 -> g_A2 slot 0 --------------------------------
__global__ void build_h0(const float* __restrict__ state0) {
    int idx = blockIdx.x * blockDim.x + threadIdx.x;
    if (idx >= BB * 64) return;
    int m = idx >> 6, k = (idx & 63) * 8;
    const float* src = state0 + (size_t)m * HH + k;
    float4 f0 = *reinterpret_cast<const float4*>(src);
    float4 f1 = *reinterpret_cast<const float4*>(src + 4);
    float fv[8] = {f0.x, f0.y, f0.z, f0.w, f1.x, f1.y, f1.z, f1.w};
    __nv_bfloat16 hv[8], lv[8];
    #pragma unroll
    for (int i = 0; i < 8; i++) {
        __nv_bfloat16 hi = __float2bfloat16(fv[i]);
        hv[i] = hi;
        lv[i] = __float2bfloat16(fv[i] - __bfloat162float(hi));
    }
    *reinterpret_cast<int4*>(&g_A2[(size_t)m * KSTORE + k])       = *reinterpret_cast<int4*>(hv);
    *reinterpret_cast<int4*>(&g_A2[(size_t)m * KSTORE + 512 + k]) = *reinterpret_cast<int4*>(lv);
}

// ---------------- prep: x-side preactivation xq[t][cta][b][32] (bias folded) --
__global__ void __launch_bounds__(256)
build_xpre(const int* __restrict__ x,
           const float* __restrict__ Wxi, const float* __restrict__ Wxf,
           const float* __restrict__ Wxo, const float* __restrict__ Wxc,
           const float* __restrict__ bi,  const float* __restrict__ bf_,
           const float* __restrict__ bo,  const float* __restrict__ bc) {
    int idx = blockIdx.x * blockDim.x + threadIdx.x;   // one float4
    if (idx >= TT * BB * 512) return;
    int f4  = idx & 7;
    int b   = (idx >> 3) & 63;
    int cta = (idx >> 9) & 63;
    int t   = idx >> 15;
    int col0 = f4 * 4;
    int g  = col0 >> 3;
    int u0 = col0 & 7;
    const float* W  = (g == 0) ? Wxi : (g == 1) ? Wxf : (g == 2) ? Wxo : Wxc;
    const float* bb = (g == 0) ? bi  : (g == 1) ? bf_ : (g == 2) ? bo  : bc;
    int tok = x[b * TT + t];
    float4 w = *reinterpret_cast<const float4*>(&W[(size_t)tok * HH + cta * 8 + u0]);
    float4 bv = *reinterpret_cast<const float4*>(&bb[cta * 8 + u0]);
    float4 o = {w.x + bv.x, w.y + bv.y, w.z + bv.z, w.w + bv.w};
    *reinterpret_cast<float4*>(&g_XQ[(size_t)idx * 4]) = o;
}

// ---------------- tensor-core persistent LSTM recurrence ---------------------
// 64 CTAs x 256 threads (8 warps = 4m x 2n). CTA owns 8 units x 4 gates.
#define HROW_B 2064
#define SM_W   (64 * HROW_B)                 // 132096
#define SM_P   (SM_W + 32 * HROW_B)          // 198144
#define SM_C   (SM_P + 64 * 32 * 4)          // 206336
#define SM_XQ  (SM_C + 512 * 4)              // 208384
#define SM_TOT (SM_XQ + 8192)                // 216576

__global__ void __launch_bounds__(256, 1)
lstm_tc(const float* __restrict__ cell0, float* __restrict__ out) {
    extern __shared__ __align__(128) char sm[];
    const uint32_t hbase = smem_u32(sm);
    const uint32_t wbase = hbase + SM_W;
    float* pbuf  = reinterpret_cast<float*>(sm + SM_P);
    float* cellb = reinterpret_cast<float*>(sm + SM_C);
    float* sxq   = reinterpret_cast<float*>(sm + SM_XQ);
    const uint32_t xqb = hbase + SM_XQ;

    const int tid = threadIdx.x;
    const int wid = tid >> 5;
    const int lid = tid & 31;
    const int cta = blockIdx.x;
    const int j0  = cta * 8;
    const int mg  = wid >> 1;
    const int ng  = wid & 1;
    const int lr  = lid & 15;
    const int lc  = (lid >> 4) * 16;
    const int eb  = tid >> 2;
    const int u0  = (tid & 3) * 2;

    unsigned genBase = 0;
    if (tid == 0) genBase = *(volatile unsigned*)&g_gen;

    // pin weights (32 rows x 2048B)
    {
        const char* src = (const char*)(g_WB + (size_t)(cta * 32) * KSTORE);
        for (int c = tid; c < 4096; c += 256) {
            int r = c >> 7, cc = c & 127;
            cp_async16(wbase + r * HROW_B + cc * 16, src + (size_t)r * 2048 + cc * 16);
        }
        asm volatile("cp.async.commit_group;" ::: "memory");
    }
    for (int i = tid; i < 512; i += 256)
        cellb[i] = cell0[(size_t)(i >> 3) * HH + j0 + (i & 7)];
    asm volatile("cp.async.wait_group 0;" ::: "memory");
    __syncthreads();

    for (int t = 0; t < TT; t++) {
        const char* Asrc = (const char*)(g_A2 + (size_t)t * BB * KSTORE);
        // group 0: k<256 halves of hi and lo regions (cc 0..31, 64..95)
        for (int c = tid; c < 4096; c += 256) {
            int r = c >> 6, q = c & 63;
            int cc = (q < 32) ? q : (q + 32);
            cp_async16(hbase + r * HROW_B + cc * 16, Asrc + (size_t)r * 2048 + cc * 16);
        }
        asm volatile("cp.async.commit_group;" ::: "memory");
        // group 1: k>=256 halves + xq prefetch
        for (int c = tid; c < 4096; c += 256) {
            int r = c >> 6, q = c & 63;
            int cc = (q < 32) ? (q + 32) : (q + 64);
            cp_async16(hbase + r * HROW_B + cc * 16, Asrc + (size_t)r * 2048 + cc * 16);
        }
        {
            const char* xs = (const char*)g_XQ + ((size_t)t * 64 + cta) * 8192;
            for (int c = tid; c < 512; c += 256)
                cp_async16(xqb + c * 16, xs + c * 16);
        }
        asm volatile("cp.async.commit_group;" ::: "memory");

        float acc0[4] = {0.f, 0.f, 0.f, 0.f};
        float acc1[4] = {0.f, 0.f, 0.f, 0.f};
        const uint32_t ha = hbase + (mg * 16 + lr) * HROW_B + lc;
        const uint32_t wa = wbase + (ng * 16 + lr) * HROW_B + lc;

        asm volatile("cp.async.wait_group 1;" ::: "memory");
        __syncthreads();
        #pragma unroll 4
        for (int kt = 0; kt < 16; kt++) {
            uint32_t ahi[4], alo[4], bhi[4], blo[4];
            ldsm_x4(ahi, ha + kt * 32);
            ldsm_x4(alo, ha + 1024 + kt * 32);
            ldsm_x4(bhi, wa + kt * 32);
            ldsm_x4(blo, wa + 1024 + kt * 32);
            mma16816(acc0, ahi, bhi[0], bhi[2]);
            mma16816(acc1, ahi, bhi[1], bhi[3]);
            mma16816(acc0, alo, bhi[0], bhi[2]);
            mma16816(acc1, alo, bhi[1], bhi[3]);
            mma16816(acc0, ahi, blo[0], blo[2]);
            mma16816(acc1, ahi, blo[1], blo[3]);
        }
        asm volatile("cp.async.wait_group 0;" ::: "memory");
        __syncthreads();
        #pragma unroll 4
        for (int kt = 16; kt < 32; kt++) {
            uint32_t ahi[4], alo[4], bhi[4], blo[4];
            ldsm_x4(ahi, ha + kt * 32);
            ldsm_x4(alo, ha + 1024 + kt * 32);
            ldsm_x4(bhi, wa + kt * 32);
            ldsm_x4(blo, wa + 1024 + kt * 32);
            mma16816(acc0, ahi, bhi[0], bhi[2]);
            mma16816(acc1, ahi, bhi[1], bhi[3]);
            mma16816(acc0, alo, bhi[0], bhi[2]);
            mma16816(acc1, alo, bhi[1], bhi[3]);
            mma16816(acc0, ahi, blo[0], blo[2]);
            mma16816(acc1, ahi, blo[1], blo[3]);
        }

        // exchange fragments
        {
            const int qr = lid >> 2;
            const int qc = (lid & 3) * 2;
            int row = mg * 16 + qr;
            int col = ng * 16 + qc;
            pbuf[row * 32 + col]           = acc0[0];
            pbuf[row * 32 + col + 1]       = acc0[1];
            pbuf[(row + 8) * 32 + col]     = acc0[2];
            pbuf[(row + 8) * 32 + col + 1] = acc0[3];
            pbuf[row * 32 + col + 8]       = acc1[0];
            pbuf[row * 32 + col + 9]       = acc1[1];
            pbuf[(row + 8) * 32 + col + 8] = acc1[2];
            pbuf[(row + 8) * 32 + col + 9] = acc1[3];
        }
        __syncthreads();

        // elementwise
        {
            const float* pr = pbuf + eb * 32;
            const float* xr = sxq  + eb * 32;
            float i0 = sigmoidf_(pr[u0]          + xr[u0]);
            float i1 = sigmoidf_(pr[u0 + 1]      + xr[u0 + 1]);
            float f0 = sigmoidf_(pr[8 + u0]      + xr[8 + u0]);
            float f1 = sigmoidf_(pr[8 + u0 + 1]  + xr[8 + u0 + 1]);
            float o0 = sigmoidf_(pr[16 + u0]     + xr[16 + u0]);
            float o1 = sigmoidf_(pr[16 + u0 + 1] + xr[16 + u0 + 1]);
            float g0 = tanhf    (pr[24 + u0]     + xr[24 + u0]);
            float g1 = tanhf    (pr[24 + u0 + 1] + xr[24 + u0 + 1]);

            float c0 = cellb[eb * 8 + u0];
            float c1 = cellb[eb * 8 + u0 + 1];
            float cn0 = fmaf(f0, c0, i0 * g0);
            float cn1 = fmaf(f1, c1, i1 * g1);
            cellb[eb * 8 + u0]     = cn0;
            cellb[eb * 8 + u0 + 1] = cn1;
            float hn0 = o0 * tanhf(cn0);
            float hn1 = o1 * tanhf(cn1);

            __nv_bfloat16 h0 = __float2bfloat16(hn0);
            __nv_bfloat16 h1 = __float2bfloat16(hn1);
            __nv_bfloat16 l0 = __float2bfloat16(hn0 - __bfloat162float(h0));
            __nv_bfloat16 l1 = __float2bfloat16(hn1 - __bfloat162float(h1));
            uint32_t hib = (uint32_t)__bfloat16_as_ushort(h0) |
                           ((uint32_t)__bfloat16_as_ushort(h1) << 16);
            uint32_t lob = (uint32_t)__bfloat16_as_ushort(l0) |
                           ((uint32_t)__bfloat16_as_ushort(l1) << 16);
            char* dst = (char*)(g_A2 + (size_t)(t + 1) * BB * KSTORE) + (size_t)eb * 2048;
            *reinterpret_cast<uint32_t*>(dst + (j0 + u0) * 2)        = hib;
            *reinterpret_cast<uint32_t*>(dst + 1024 + (j0 + u0) * 2) = lob;
            if (t == TT - 1) {
                float2 hv = {hn0, hn1};
                *reinterpret_cast<float2*>(out + OUT_STATE_OFF + (size_t)eb * HH + j0 + u0) = hv;
            }
        }
        __threadfence();
        __syncthreads();

        if (t < TT - 1) {
            if (tid == 0) {
                unsigned arr = atomicAdd(&g_cnt, 1u);
                if (arr == gridDim.x - 1) {
                    atomicExch(&g_cnt, 0u);
                    __threadfence();
                    atomicAdd(&g_gen, 1u);
                } else {
                    unsigned target = (unsigned)(t + 1);
                    while ((*(volatile unsigned*)&g_gen) - genBase < target)
                        __nanosleep(40);
                }
                __threadfence();
            }
            __syncthreads();
        }
    }

    for (int i = tid; i < 512; i += 256)
        out[OUT_CELL_OFF + (size_t)(i >> 3) * HH + j0 + (i & 7)] = cellb[i];
}

// ---------------- output GEMM: 128x128 tiles, 2 CTAs/SM ----------------------
__global__ void __launch_bounds__(256, 2)
gemm_mma(const float* __restrict__ bq, float* __restrict__ out) {
    extern __shared__ __align__(128) char dsm[];
    const uint32_t sbase = smem_u32(dsm);
    const int tid = threadIdx.x;
    const int wid = tid >> 5;
    const int lid = tid & 31;
    const int nt  = blockIdx.x;
    const int mt  = blockIdx.y;
    const int m0  = mt * TM2;
    const int n0  = nt * TN2;
    const int mg  = (wid >> 1) * 32;   // warp rows
    const int ng  = (wid & 1) * 64;    // warp cols

    const __nv_bfloat16* gA = g_A2  + (size_t)(BB + m0) * KSTORE;  // skip slot 0
    const __nv_bfloat16* gB = g_B2T + (size_t)n0 * KSTORE;

    auto a_off = [](int kt) { return ((kt < 32) ? kt : kt - 32) * TK; };
    auto b_off = [](int kt) { return ((kt < 16) ? kt : kt - 16) * TK; };

    float acc[2][8][4];
    #pragma unroll
    for (int i = 0; i < 2; i++)
        #pragma unroll
        for (int j = 0; j < 8; j++)
            #pragma unroll
            for (int q = 0; q < 4; q++) acc[i][j][q] = 0.0f;

    auto load_stage = [&](int kt, int s) {
        uint32_t dA = sbase + s * G_STG_B;
        uint32_t dB = dA + G_AST_B;
        int ao = a_off(kt), bo = b_off(kt);
        #pragma unroll
        for (int c = 0; c < 2; c++) {          // A: 512 chunks
            int ch = c * 256 + tid;
            int row = ch >> 2, cc = ch & 3;
            cp_async16(dA + row * G_ROW_B + cc * 16,
                       gA + (size_t)row * KSTORE + ao + cc * 8);
        }
        #pragma unroll
        for (int c = 0; c < 2; c++) {          // B: 512 chunks
            int ch = c * 256 + tid;
            int row = ch >> 2, cc = ch & 3;
            cp_async16(dB + row * G_ROW_B + cc * 16,
                       gB + (size_t)row * KSTORE + bo + cc * 8);
        }
        asm volatile("cp.async.commit_group;" ::: "memory");
    };

    #pragma unroll
    for (int s = 0; s < STAGES - 1; s++) load_stage(s, s);

    const int lr = lid & 15;
    const int lc = (lid >> 4) * 16;

    for (int t = 0; t < KTILES; t++) {
        const int s = t & (STAGES - 1);
        if (t <= KTILES - 3)      asm volatile("cp.async.wait_group 2;" ::: "memory");
        else if (t == KTILES - 2) asm volatile("cp.async.wait_group 1;" ::: "memory");
        else                      asm volatile("cp.async.wait_group 0;" ::: "memory");
        __syncthreads();

        const int tn = t + STAGES - 1;
        if (tn < KTILES) load_stage(tn, tn & (STAGES - 1));

        const uint32_t Ab = sbase + s * G_STG_B;
        const uint32_t Bb = Ab + G_AST_B;
        #pragma unroll
        for (int ks2 = 0; ks2 < 2; ks2++) {
            uint32_t af[2][4], bf[4][4];
            #pragma unroll
            for (int i = 0; i < 2; i++)
                ldsm_x4(af[i], Ab + (mg + i * 16 + lr) * G_ROW_B + ks2 * 32 + lc);
            #pragma unroll
            for (int j = 0; j < 4; j++)
                ldsm_x4(bf[j], Bb + (ng + j * 16 + lr) * G_ROW_B + ks2 * 32 + lc);
            #pragma unroll
            for (int i = 0; i < 2; i++)
                #pragma unroll
                for (int j = 0; j < 4; j++) {
                    mma16816(acc[i][2 * j],     af[i], bf[j][0], bf[j][2]);
                    mma16816(acc[i][2 * j + 1], af[i], bf[j][1], bf[j][3]);
                }
        }
    }

    const int qr = lid >> 2;
    const int qc = (lid & 3) * 2;
    float2 bias2[8];
    #pragma unroll
    for (int j = 0; j < 8; j++) {
        int n = n0 + ng + j * 8 + qc;
        bias2[j].x = (n < VV)     ? bq[n]     : 0.0f;
        bias2[j].y = (n + 1 < VV) ? bq[n + 1] : 0.0f;
    }
    #pragma unroll
    for (int i = 0; i < 2; i++) {
        int mrow = m0 + mg + i * 16 + qr;
        #pragma unroll
        for (int j = 0; j < 8; j++) {
            int n = n0 + ng + j * 8 + qc;
            if (n < VV) {
                float2 v0 = {acc[i][j][0] + bias2[j].x, acc[i][j][1] + bias2[j].y};
                float2 v1 = {acc[i][j][2] + bias2[j].x, acc[i][j][3] + bias2[j].y};
                *reinterpret_cast<float2*>(out + (size_t)mrow * VV + n) = v0;
                *reinterpret_cast<float2*>(out + (size_t)(mrow + 8) * VV + n) = v1;
            }
        }
    }
}

// ---------------- launch ----------------
extern "C" void kernel_launch(void* const* d_in, const int* in_sizes, int n_in,
                              void* d_out, int out_size) {
    const int*   x     = (const int*)  d_in[0];
    const float* state = (const float*)d_in[1];
    const float* cell  = (const float*)d_in[2];
    const float* W_xi  = (const float*)d_in[3];
    const float* W_hi  = (const float*)d_in[4];
    const float* b_i   = (const float*)d_in[5];
    const float* W_xf  = (const float*)d_in[6];
    const float* W_hf  = (const float*)d_in[7];
    const float* b_f   = (const float*)d_in[8];
    const float* W_xo  = (const float*)d_in[9];
    const float* W_ho  = (const float*)d_in[10];
    const float* b_o   = (const float*)d_in[11];
    const float* W_xc  = (const float*)d_in[12];
    const float* W_hc  = (const float*)d_in[13];
    const float* b_c   = (const float*)d_in[14];
    const float* W_hq  = (const float*)d_in[15];
    const float* b_q   = (const float*)d_in[16];
    float* out = (float*)d_out;

    cudaFuncSetAttribute(lstm_tc, cudaFuncAttributeMaxDynamicSharedMemorySize, SM_TOT);
    size_t b2t_smem = 64 * 257 * sizeof(float);
    cudaFuncSetAttribute(build_b2t, cudaFuncAttributeMaxDynamicSharedMemorySize,
                         (int)b2t_smem);
    size_t gemm_smem = (size_t)STAGES * G_STG_B;   // 81920
    cudaFuncSetAttribute(gemm_mma, cudaFuncAttributeMaxDynamicSharedMemorySize,
                         (int)gemm_smem);

    build_whb<<<dim3(16, 16, 4), 256>>>(W_hi, W_hf, W_ho, W_hc);
    build_b2t<<<dim3(8, NTILES / 2), 256, b2t_smem>>>(W_hq);
    build_h0<<<16, 256>>>(state);
    build_xpre<<<(TT * BB * 512 + 255) / 256, 256>>>(x, W_xi, W_xf, W_xo, W_xc,
                                                     b_i, b_f, b_o, b_c);
    lstm_tc<<<64, 256, SM_TOT>>>(cell, out);
    gemm_mma<<<dim3(NTILES, MTILES), 256, gemm_smem>>>(b_q, out);
}

// round 9
// speedup vs baseline: 1.1564x; 1.0639x over previous
#include <cuda_runtime.h>
#include <cuda_bf16.h>
#include <cstdint>

// ---------------- problem constants ----------------
#define TT   128
#define BB   64
#define HH   512
#define VV   10000

#define KSTORE 1024          // split-bf16 storage K: [hi(512)|lo(512)]
#define KTILES 48            // logical K' = 1536 in 32-elem tiles
#define MTILES 64            // 8192 / 128
#define NTILES 40            // 40*256 = 10240
#define TM     128
#define TN     256

#define OUT_STATE_OFF 81920000u
#define OUT_CELL_OFF  81952768u

// swizzles: swzH for 2048B rows (rec h/W tiles), swzG for 64B rows (gemm blocks)
__device__ __forceinline__ uint32_t swzH(uint32_t off) { return off ^ (((off >> 11) & 7u) << 4); }
__device__ __forceinline__ uint32_t swzG(uint32_t off) { return off ^ ((off >> 3) & 0x30u); }

// ---------------- device scratch ----------------
__device__ __align__(16) char  g_A2[(size_t)(TT + 1) * BB * 2048];   // h slots, swzH rows
__device__ __align__(16) char  g_GA[(size_t)MTILES * 32 * 8192];     // gemm A blocks, swzG
__device__ __align__(16) char  g_GB[(size_t)NTILES * 32 * 16384];    // gemm B blocks, swzG
__device__ __align__(16) char  g_WB[(size_t)64 * 65536];             // rec W regions, swzH
__device__ __align__(16) float g_XQ[(size_t)TT * BB * 2048];         // x-preact (bias folded)
__device__ unsigned g_cnt = 0;
__device__ unsigned g_gen = 0;

__device__ __forceinline__ float sigmoidf_(float x) { return 1.0f / (1.0f + expf(-x)); }

__device__ __forceinline__ uint32_t smem_u32(const void* p) {
    uint32_t a;
    asm("{ .reg .u64 t; cvta.to.shared.u64 t, %1; cvt.u32.u64 %0, t; }" : "=r"(a) : "l"(p));
    return a;
}
__device__ __forceinline__ void cp_async16(uint32_t dst, const void* src) {
    asm volatile("cp.async.cg.shared.global [%0], [%1], 16;" :: "r"(dst), "l"(src));
}
__device__ __forceinline__ void bulk_g2s(uint32_t dst, const void* src, uint32_t bytes, uint32_t mbar) {
    asm volatile("cp.async.bulk.shared::cluster.global.mbarrier::complete_tx::bytes "
                 "[%0], [%1], %2, [%3];"
                 :: "r"(dst), "l"(src), "r"(bytes), "r"(mbar) : "memory");
}
#define MBARRIER_INIT(addr, cnt) \
    asm volatile("mbarrier.init.shared.b64 [%0], %1;" :: "r"(addr), "r"(cnt) : "memory")
#define MBARRIER_EXPECT_TX(addr, tx) \
    asm volatile("mbarrier.arrive.expect_tx.shared.b64 _, [%0], %1;" :: "r"(addr), "r"(tx) : "memory")
#define MBARRIER_WAIT_PARITY(mbar, par) do {                                    \
    uint32_t _m = (mbar); uint32_t _p = (par); uint32_t _d;                     \
    asm volatile("{\n\t.reg .pred p;\n\t"                                       \
        "mbarrier.try_wait.parity.acquire.cta.shared::cta.b64 p, [%1], %2;\n\t" \
        "selp.b32 %0, 1, 0, p;\n\t}" : "=r"(_d) : "r"(_m), "r"(_p) : "memory"); \
    if (!_d) {                                                                  \
        asm volatile("{\n\t.reg .pred P1;\n\t"                                  \
        "WL_%=:\n\t"                                                            \
        "mbarrier.try_wait.parity.acquire.cta.shared::cta.b64 P1, [%0], %1, 0x989680;\n\t" \
        "@P1 bra.uni WD_%=;\n\t"                                                \
        "bra.uni WL_%=;\n\t"                                                    \
        "WD_%=:\n\t}" :: "r"(_m), "r"(_p) : "memory");                          \
    } } while (0)

__device__ __forceinline__ void ldsm_x4(uint32_t* r, uint32_t addr) {
    asm volatile("ldmatrix.sync.aligned.m8n8.x4.shared.b16 {%0,%1,%2,%3}, [%4];"
                 : "=r"(r[0]), "=r"(r[1]), "=r"(r[2]), "=r"(r[3]) : "r"(addr));
}
__device__ __forceinline__ void mma16816(float* c, const uint32_t* a, uint32_t b0, uint32_t b1) {
    asm volatile("mma.sync.aligned.m16n8k16.row.col.f32.bf16.bf16.f32 "
                 "{%0,%1,%2,%3}, {%4,%5,%6,%7}, {%8,%9}, {%0,%1,%2,%3};"
                 : "+f"(c[0]), "+f"(c[1]), "+f"(c[2]), "+f"(c[3])
                 : "r"(a[0]), "r"(a[1]), "r"(a[2]), "r"(a[3]), "r"(b0), "r"(b1));
}

// ---------------- prep1: W_h* -> g_WB (swzH) and W_hq -> g_GB blocks (swzG) ---
// blocks 0..1023: whb (kt,jt,g); blocks 1024..2303: b2t (kc 0..31, nt 0..39)
__global__ void __launch_bounds__(256)
prep1(const float* __restrict__ Whq,
      const float* __restrict__ Wi, const float* __restrict__ Wf,
      const float* __restrict__ Wo, const float* __restrict__ Wc) {
    __shared__ float tile[32 * 257];
    const int blk = blockIdx.x;
    const int tid = threadIdx.x;
    if (blk < 1024) {
        const int kt = blk & 15, jt = (blk >> 4) & 15, g = blk >> 8;
        const float* W = (g == 0) ? Wi : (g == 1) ? Wf : (g == 2) ? Wo : Wc;
        for (int i = tid; i < 1024; i += 256) {
            int kk = i >> 5, jj = i & 31;
            tile[kk * 33 + jj] = W[(kt * 32 + kk) * HH + jt * 32 + jj];
        }
        __syncthreads();
        for (int i = tid; i < 1024; i += 256) {
            int jj = i >> 5, kk = i & 31;
            float w = tile[kk * 33 + jj];
            int j   = jt * 32 + jj;
            int cta = j >> 3;
            int row = g * 8 + (j & 7);
            uint32_t offh = (uint32_t)(row * 2048 + (kt * 32 + kk) * 2);
            __nv_bfloat16 hi = __float2bfloat16(w);
            __nv_bfloat16 lo = __float2bfloat16(w - __bfloat162float(hi));
            char* base = g_WB + (size_t)cta * 65536;
            *reinterpret_cast<__nv_bfloat16*>(base + swzH(offh))        = hi;
            *reinterpret_cast<__nv_bfloat16*>(base + swzH(offh + 1024)) = lo;
        }
    } else {
        const int b  = blk - 1024;
        const int kc = b & 31;
        const int nt = b >> 5;
        const bool lo = (kc >= 16);
        const int ksrc = (lo ? (kc - 16) : kc) * 32;
        for (int i = tid; i < 32 * 256; i += 256) {
            int kk = i >> 8, nn = i & 255;
            int n = nt * 256 + nn;
            tile[kk * 257 + nn] = (n < VV) ? Whq[(ksrc + kk) * VV + n] : 0.0f;
        }
        __syncthreads();
        char* blkbase = g_GB + (size_t)(nt * 32 + kc) * 16384;
        for (int c = tid; c < 1024; c += 256) {
            int row = c >> 2, ch = c & 3;
            __nv_bfloat16 v[8];
            #pragma unroll
            for (int i = 0; i < 8; i++) {
                float w = tile[(ch * 8 + i) * 257 + row];
                __nv_bfloat16 hi = __float2bfloat16(w);
                v[i] = lo ? __float2bfloat16(w - __bfloat162float(hi)) : hi;
            }
            uint32_t off = (uint32_t)(row * 64 + ch * 16);
            *reinterpret_cast<int4*>(blkbase + swzG(off)) = *reinterpret_cast<int4*>(v);
        }
    }
}

// ---------------- prep2: x-preacts (bias folded) + state0 -> slot 0 ----------
__global__ void __launch_bounds__(256)
prep2(const int* __restrict__ x, const float* __restrict__ state0,
      const float* __restrict__ Wxi, const float* __restrict__ Wxf,
      const float* __restrict__ Wxo, const float* __restrict__ Wxc,
      const float* __restrict__ bi,  const float* __restrict__ bf_,
      const float* __restrict__ bo,  const float* __restrict__ bc) {
    const int blk = blockIdx.x;
    const int tid = threadIdx.x;
    if (blk < 16384) {
        int idx = blk * 256 + tid;           // one float4 of xq
        int f4  = idx & 7;
        int b   = (idx >> 3) & 63;
        int cta = (idx >> 9) & 63;
        int t   = idx >> 15;
        int col0 = f4 * 4;
        int g  = col0 >> 3;
        int u0 = col0 & 7;
        const float* W  = (g == 0) ? Wxi : (g == 1) ? Wxf : (g == 2) ? Wxo : Wxc;
        const float* bb = (g == 0) ? bi  : (g == 1) ? bf_ : (g == 2) ? bo  : bc;
        int tok = x[b * TT + t];
        float4 w  = *reinterpret_cast<const float4*>(&W[(size_t)tok * HH + cta * 8 + u0]);
        float4 bv = *reinterpret_cast<const float4*>(&bb[cta * 8 + u0]);
        float4 o = {w.x + bv.x, w.y + bv.y, w.z + bv.z, w.w + bv.w};
        *reinterpret_cast<float4*>(&g_XQ[(size_t)idx * 4]) = o;
    } else {
        int idx = (blk - 16384) * 256 + tid;   // one 8-float chunk of state0
        if (idx >= BB * 64) return;
        int m = idx >> 6, kp = (idx & 63) * 8;
        const float* src = state0 + (size_t)m * HH + kp;
        float4 f0 = *reinterpret_cast<const float4*>(src);
        float4 f1 = *reinterpret_cast<const float4*>(src + 4);
        float fv[8] = {f0.x, f0.y, f0.z, f0.w, f1.x, f1.y, f1.z, f1.w};
        __nv_bfloat16 hv[8], lv[8];
        #pragma unroll
        for (int i = 0; i < 8; i++) {
            __nv_bfloat16 hi = __float2bfloat16(fv[i]);
            hv[i] = hi;
            lv[i] = __float2bfloat16(fv[i] - __bfloat162float(hi));
        }
        uint32_t off = (uint32_t)(m * 2048 + kp * 2);
        *reinterpret_cast<int4*>(g_A2 + swzH(off))        = *reinterpret_cast<int4*>(hv);
        *reinterpret_cast<int4*>(g_A2 + swzH(off + 1024)) = *reinterpret_cast<int4*>(lv);
    }
}

// ---------------- tensor-core persistent LSTM recurrence (bulk loads) --------
// 64 CTAs x 256 threads (8 warps = 4m x 2n). CTA owns 8 units x 4 gates.
#define SM_H   0                // 131072 (h: 64 rows x 2048B, swzH)
#define SM_W   131072           // 65536 (W: 32 rows x 2048B, swzH)
#define SM_XQ  196608           // 8192
#define SM_P   204800           // 8192 (pbuf 64x32 f32)
#define SM_C   212992           // 2048 (cell)
#define SM_TOT 215040

__global__ void __launch_bounds__(256, 1)
lstm_tc(const float* __restrict__ cell0, float* __restrict__ out) {
    extern __shared__ __align__(128) char sm[];
    __shared__ __align__(8) uint64_t s_bar;
    const uint32_t hbase = smem_u32(sm);
    const uint32_t wbase = hbase + SM_W;
    const uint32_t xqb   = hbase + SM_XQ;
    const uint32_t bar   = smem_u32(&s_bar);
    float* pbuf  = reinterpret_cast<float*>(sm + SM_P);
    float* cellb = reinterpret_cast<float*>(sm + SM_C);
    float* sxq   = reinterpret_cast<float*>(sm + SM_XQ);

    const int tid = threadIdx.x;
    const int wid = tid >> 5;
    const int lid = tid & 31;
    const int cta = blockIdx.x;
    const int j0  = cta * 8;
    const int mg  = wid >> 1;
    const int ng  = wid & 1;
    const int lr  = lid & 15;
    const int lc  = (lid >> 4) * 16;
    const int eb  = tid >> 2;
    const int u0  = (tid & 3) * 2;
    const int j   = j0 + u0;

    unsigned genBase = 0;
    if (tid == 0) genBase = *(volatile unsigned*)&g_gen;
    if (tid == 0) MBARRIER_INIT(bar, 1);

    // pin weights (one-time, 64KB linear copy of pre-swizzled region)
    {
        const char* src = g_WB + (size_t)cta * 65536;
        for (int c = tid; c < 4096; c += 256)
            cp_async16(wbase + c * 16, src + (size_t)c * 16);
        asm volatile("cp.async.commit_group;" ::: "memory");
    }
    for (int i = tid; i < 512; i += 256)
        cellb[i] = cell0[(size_t)(i >> 3) * HH + j0 + (i & 7)];
    asm volatile("cp.async.wait_group 0;" ::: "memory");
    __syncthreads();

    const uint32_t rowA = (uint32_t)((mg * 16 + lr) * 2048);
    const uint32_t rowW = (uint32_t)((ng * 16 + lr) * 2048);

    for (int t = 0; t < TT; t++) {
        // ---- one bulk for h (128KB) + one for xq (8KB) ----
        if (tid == 0) {
            MBARRIER_EXPECT_TX(bar, 131072u + 8192u);
            bulk_g2s(hbase, g_A2 + (size_t)t * 131072, 131072u, bar);
            bulk_g2s(xqb, (const char*)g_XQ + ((size_t)(t * 64 + cta)) * 8192, 8192u, bar);
        }
        MBARRIER_WAIT_PARITY(bar, (uint32_t)(t & 1));
        __syncthreads();

        // ---- 3-product split-bf16 mma ----
        float acc0[4] = {0.f, 0.f, 0.f, 0.f};
        float acc1[4] = {0.f, 0.f, 0.f, 0.f};
        #pragma unroll 4
        for (int kt = 0; kt < 32; kt++) {
            uint32_t ahi[4], alo[4], bhi[4], blo[4];
            uint32_t ca = rowA + kt * 32 + lc;
            uint32_t cw = rowW + kt * 32 + lc;
            ldsm_x4(ahi, hbase + swzH(ca));
            ldsm_x4(alo, hbase + swzH(ca + 1024));
            ldsm_x4(bhi, wbase + swzH(cw));
            ldsm_x4(blo, wbase + swzH(cw + 1024));
            mma16816(acc0, ahi, bhi[0], bhi[2]);
            mma16816(acc1, ahi, bhi[1], bhi[3]);
            mma16816(acc0, alo, bhi[0], bhi[2]);
            mma16816(acc1, alo, bhi[1], bhi[3]);
            mma16816(acc0, ahi, blo[0], blo[2]);
            mma16816(acc1, ahi, blo[1], blo[3]);
        }

        // ---- exchange fragments ----
        {
            const int qr = lid >> 2;
            const int qc = (lid & 3) * 2;
            int row = mg * 16 + qr;
            int col = ng * 16 + qc;
            pbuf[row * 32 + col]           = acc0[0];
            pbuf[row * 32 + col + 1]       = acc0[1];
            pbuf[(row + 8) * 32 + col]     = acc0[2];
            pbuf[(row + 8) * 32 + col + 1] = acc0[3];
            pbuf[row * 32 + col + 8]       = acc1[0];
            pbuf[row * 32 + col + 9]       = acc1[1];
            pbuf[(row + 8) * 32 + col + 8] = acc1[2];
            pbuf[(row + 8) * 32 + col + 9] = acc1[3];
        }
        __syncthreads();

        // ---- elementwise + dual-layout h writes ----
        {
            const float* pr = pbuf + eb * 32;
            const float* xr = sxq  + eb * 32;
            float i0 = sigmoidf_(pr[u0]          + xr[u0]);
            float i1 = sigmoidf_(pr[u0 + 1]      + xr[u0 + 1]);
            float f0 = sigmoidf_(pr[8 + u0]      + xr[8 + u0]);
            float f1 = sigmoidf_(pr[8 + u0 + 1]  + xr[8 + u0 + 1]);
            float o0 = sigmoidf_(pr[16 + u0]     + xr[16 + u0]);
            float o1 = sigmoidf_(pr[16 + u0 + 1] + xr[16 + u0 + 1]);
            float g0 = tanhf    (pr[24 + u0]     + xr[24 + u0]);
            float g1 = tanhf    (pr[24 + u0 + 1] + xr[24 + u0 + 1]);

            float c0 = cellb[eb * 8 + u0];
            float c1 = cellb[eb * 8 + u0 + 1];
            float cn0 = fmaf(f0, c0, i0 * g0);
            float cn1 = fmaf(f1, c1, i1 * g1);
            cellb[eb * 8 + u0]     = cn0;
            cellb[eb * 8 + u0 + 1] = cn1;
            float hn0 = o0 * tanhf(cn0);
            float hn1 = o1 * tanhf(cn1);

            __nv_bfloat16 h0 = __float2bfloat16(hn0);
            __nv_bfloat16 h1 = __float2bfloat16(hn1);
            __nv_bfloat16 l0 = __float2bfloat16(hn0 - __bfloat162float(h0));
            __nv_bfloat16 l1 = __float2bfloat16(hn1 - __bfloat162float(h1));
            uint32_t hib = (uint32_t)__bfloat16_as_ushort(h0) |
                           ((uint32_t)__bfloat16_as_ushort(h1) << 16);
            uint32_t lob = (uint32_t)__bfloat16_as_ushort(l0) |
                           ((uint32_t)__bfloat16_as_ushort(l1) << 16);
            // recurrence layout (slot t+1, swzH)
            char* dst = g_A2 + (size_t)(t + 1) * 131072;
            uint32_t offh = (uint32_t)(eb * 2048 + j * 2);
            *reinterpret_cast<uint32_t*>(dst + swzH(offh))        = hib;
            *reinterpret_cast<uint32_t*>(dst + swzH(offh + 1024)) = lob;
            // gemm block layout (swzG)
            int mt  = t >> 1;
            int row = ((t & 1) << 6) | eb;
            int kcH = j >> 5;
            uint32_t offg = (uint32_t)(row * 64 + ((j & 31) * 2));
            char* ga  = g_GA + (size_t)(mt * 32 + kcH) * 8192;
            char* gal = g_GA + (size_t)(mt * 32 + 16 + kcH) * 8192;
            *reinterpret_cast<uint32_t*>(ga  + swzG(offg)) = hib;
            *reinterpret_cast<uint32_t*>(gal + swzG(offg)) = lob;
            if (t == TT - 1) {
                float2 hv = {hn0, hn1};
                *reinterpret_cast<float2*>(out + OUT_STATE_OFF + (size_t)eb * HH + j) = hv;
            }
        }
        __threadfence();
        __syncthreads();

        // ---- software grid barrier ----
        if (t < TT - 1) {
            if (tid == 0) {
                unsigned arr = atomicAdd(&g_cnt, 1u);
                if (arr == gridDim.x - 1) {
                    atomicExch(&g_cnt, 0u);
                    __threadfence();
                    atomicAdd(&g_gen, 1u);
                } else {
                    unsigned target = (unsigned)(t + 1);
                    while ((*(volatile unsigned*)&g_gen) - genBase < target)
                        __nanosleep(40);
                }
                __threadfence();
            }
            __syncthreads();
        }
    }

    for (int i = tid; i < 512; i += 256)
        out[OUT_CELL_OFF + (size_t)(i >> 3) * HH + j0 + (i & 7)] = cellb[i];
}

// ---------------- output GEMM: 128x256 tiles, bulk-fed 3-stage pipeline ------
#define GSTAGES 3
#define GA_B 8192
#define GB_B 16384
#define GST_B (GA_B + GB_B)     // 24576

__global__ void __launch_bounds__(256, 1)
gemm_mma(const float* __restrict__ bq, float* __restrict__ out) {
    extern __shared__ __align__(128) char dsm[];
    __shared__ __align__(8) uint64_t s_gbar[GSTAGES];
    const uint32_t sbase = smem_u32(dsm);
    const uint32_t bar0  = smem_u32(&s_gbar[0]);
    const int tid = threadIdx.x;
    const int wid = tid >> 5;
    const int lid = tid & 31;
    const int nt  = blockIdx.x;
    const int mt  = blockIdx.y;
    const int m0  = mt * TM;
    const int n0  = nt * TN;
    const int wm  = (wid >> 2) * 64;
    const int wn  = (wid & 3) * 64;
    const int lr  = lid & 15;
    const int lc  = (lid >> 4) * 16;

    if (tid == 0)
        for (int s = 0; s < GSTAGES; s++) MBARRIER_INIT(bar0 + s * 8, 1);
    __syncthreads();

    auto akc = [](int kt) { return (kt < 32) ? kt : kt - 32; };
    auto bkc = [](int kt) { return (kt < 16) ? kt : kt - 16; };
    auto fill = [&](int kt, int s) {
        if (tid == 0) {
            uint32_t b = bar0 + s * 8;
            MBARRIER_EXPECT_TX(b, (uint32_t)GST_B);
            bulk_g2s(sbase + s * GST_B,
                     g_GA + (size_t)(mt * 32 + akc(kt)) * GA_B, GA_B, b);
            bulk_g2s(sbase + s * GST_B + GA_B,
                     g_GB + (size_t)(nt * 32 + bkc(kt)) * GB_B, GB_B, b);
        }
    };

    #pragma unroll
    for (int s = 0; s < GSTAGES; s++) fill(s, s);

    float acc[4][8][4];
    #pragma unroll
    for (int i = 0; i < 4; i++)
        #pragma unroll
        for (int jn = 0; jn < 8; jn++)
            #pragma unroll
            for (int q = 0; q < 4; q++) acc[i][jn][q] = 0.0f;

    for (int t = 0; t < KTILES; t++) {
        const int s = t % GSTAGES;
        MBARRIER_WAIT_PARITY(bar0 + s * 8, (uint32_t)((t / GSTAGES) & 1));

        const uint32_t Ab = sbase + s * GST_B;
        const uint32_t Bb = Ab + GA_B;
        #pragma unroll
        for (int ks2 = 0; ks2 < 2; ks2++) {
            uint32_t af[4][4], bf[4][4];
            #pragma unroll
            for (int i = 0; i < 4; i++)
                ldsm_x4(af[i], Ab + swzG((uint32_t)((wm + i * 16 + lr) * 64 + ks2 * 32 + lc)));
            #pragma unroll
            for (int jn = 0; jn < 4; jn++)
                ldsm_x4(bf[jn], Bb + swzG((uint32_t)((wn + jn * 16 + lr) * 64 + ks2 * 32 + lc)));
            #pragma unroll
            for (int i = 0; i < 4; i++)
                #pragma unroll
                for (int jn = 0; jn < 4; jn++) {
                    mma16816(acc[i][2 * jn],     af[i], bf[jn][0], bf[jn][2]);
                    mma16816(acc[i][2 * jn + 1], af[i], bf[jn][1], bf[jn][3]);
                }
        }
        __syncthreads();
        if (t + GSTAGES < KTILES) fill(t + GSTAGES, s);
    }

    // epilogue
    const int qr = lid >> 2;
    const int qc = (lid & 3) * 2;
    float2 bias2[8];
    #pragma unroll
    for (int jn = 0; jn < 8; jn++) {
        int n = n0 + wn + jn * 8 + qc;
        bias2[jn].x = (n < VV)     ? bq[n]     : 0.0f;
        bias2[jn].y = (n + 1 < VV) ? bq[n + 1] : 0.0f;
    }
    #pragma unroll
    for (int i = 0; i < 4; i++) {
        int mrow = m0 + wm + i * 16 + qr;
        #pragma unroll
        for (int jn = 0; jn < 8; jn++) {
            int n = n0 + wn + jn * 8 + qc;
            if (n < VV) {
                float2 v0 = {acc[i][jn][0] + bias2[jn].x, acc[i][jn][1] + bias2[jn].y};
                float2 v1 = {acc[i][jn][2] + bias2[jn].x, acc[i][jn][3] + bias2[jn].y};
                *reinterpret_cast<float2*>(out + (size_t)mrow * VV + n) = v0;
                *reinterpret_cast<float2*>(out + (size_t)(mrow + 8) * VV + n) = v1;
            }
        }
    }
}

// ---------------- launch ----------------
extern "C" void kernel_launch(void* const* d_in, const int* in_sizes, int n_in,
                              void* d_out, int out_size) {
    const int*   x     = (const int*)  d_in[0];
    const float* state = (const float*)d_in[1];
    const float* cell  = (const float*)d_in[2];
    const float* W_xi  = (const float*)d_in[3];
    const float* W_hi  = (const float*)d_in[4];
    const float* b_i   = (const float*)d_in[5];
    const float* W_xf  = (const float*)d_in[6];
    const float* W_hf  = (const float*)d_in[7];
    const float* b_f   = (const float*)d_in[8];
    const float* W_xo  = (const float*)d_in[9];
    const float* W_ho  = (const float*)d_in[10];
    const float* b_o   = (const float*)d_in[11];
    const float* W_xc  = (const float*)d_in[12];
    const float* W_hc  = (const float*)d_in[13];
    const float* b_c   = (const float*)d_in[14];
    const float* W_hq  = (const float*)d_in[15];
    const float* b_q   = (const float*)d_in[16];
    float* out = (float*)d_out;

    cudaFuncSetAttribute(lstm_tc, cudaFuncAttributeMaxDynamicSharedMemorySize, SM_TOT);
    cudaFuncSetAttribute(gemm_mma, cudaFuncAttributeMaxDynamicSharedMemorySize,
                         GSTAGES * GST_B);

    prep1<<<1024 + 32 * NTILES, 256>>>(W_hq, W_hi, W_hf, W_ho, W_hc);
    prep2<<<16384 + 16, 256>>>(x, state, W_xi, W_xf, W_xo, W_xc,
                               b_i, b_f, b_o, b_c);
    lstm_tc<<<64, 256, SM_TOT>>>(cell, out);
    gemm_mma<<<dim3(NTILES, MTILES), 256, GSTAGES * GST_B>>>(b_q, out);
}

// round 10
// speedup vs baseline: 1.4527x; 1.2563x over previous
#include <cuda_runtime.h>
#include <cuda_bf16.h>
#include <cstdint>

// ---------------- problem constants ----------------
#define TT   128
#define BB   64
#define HH   512
#define VV   10000

#define KTILES 48            // logical K' = 1536 in 32-elem tiles
#define MTILES 64            // 8192 / 128
#define NTILES 40            // 40*256 = 10240
#define TM     128
#define TN     256

#define REC_CTAS  64
#define ALL_CTAS  148
#define GEMM_CTAS (ALL_CTAS - REC_CTAS)   // 84
#define SPLIT_Q   2304                    // tiles 0..2303 -> gemm CTAs; 2304..2559 -> rec CTAs (4 each)

#define OUT_STATE_OFF 81920000u
#define OUT_CELL_OFF  81952768u

// swizzles: swzH for 2048B rows (rec h/W tiles), swzG for 64B rows (gemm blocks)
__device__ __forceinline__ uint32_t swzH(uint32_t off) { return off ^ (((off >> 11) & 7u) << 4); }
__device__ __forceinline__ uint32_t swzG(uint32_t off) { return off ^ ((off >> 3) & 0x30u); }

// ---------------- device scratch ----------------
__device__ __align__(16) char  g_A2[(size_t)(TT + 1) * BB * 2048];   // h slots, swzH rows
__device__ __align__(16) char  g_GA[(size_t)MTILES * 32 * 8192];     // gemm A blocks, swzG
__device__ __align__(16) char  g_GB[(size_t)NTILES * 32 * 16384];    // gemm B blocks, swzG
__device__ __align__(16) char  g_WB[(size_t)64 * 65536];             // rec W regions, swzH
__device__ __align__(16) float g_XQ[(size_t)TT * BB * 2048];         // x-preact (bias folded)
__device__ unsigned g_cnt  = 0;   // rec step barrier counter (64)
__device__ unsigned g_cnt0 = 0;   // start barrier counter (148)
__device__ unsigned g_gen  = 0;   // monotonic progress counter

__device__ __forceinline__ float sigmoidf_(float x) { return 1.0f / (1.0f + expf(-x)); }

__device__ __forceinline__ uint32_t smem_u32(const void* p) {
    uint32_t a;
    asm("{ .reg .u64 t; cvta.to.shared.u64 t, %1; cvt.u32.u64 %0, t; }" : "=r"(a) : "l"(p));
    return a;
}
__device__ __forceinline__ void cp_async16(uint32_t dst, const void* src) {
    asm volatile("cp.async.cg.shared.global [%0], [%1], 16;" :: "r"(dst), "l"(src));
}
__device__ __forceinline__ void bulk_g2s(uint32_t dst, const void* src, uint32_t bytes, uint32_t mbar) {
    asm volatile("cp.async.bulk.shared::cluster.global.mbarrier::complete_tx::bytes "
                 "[%0], [%1], %2, [%3];"
                 :: "r"(dst), "l"(src), "r"(bytes), "r"(mbar) : "memory");
}
#define MBARRIER_INIT(addr, cnt) \
    asm volatile("mbarrier.init.shared.b64 [%0], %1;" :: "r"(addr), "r"(cnt) : "memory")
#define MBARRIER_EXPECT_TX(addr, tx) \
    asm volatile("mbarrier.arrive.expect_tx.shared.b64 _, [%0], %1;" :: "r"(addr), "r"(tx) : "memory")
#define MBARRIER_WAIT_PARITY(mbar, par) do {                                    \
    uint32_t _m = (mbar); uint32_t _p = (par); uint32_t _d;                     \
    asm volatile("{\n\t.reg .pred p;\n\t"                                       \
        "mbarrier.try_wait.parity.acquire.cta.shared::cta.b64 p, [%1], %2;\n\t" \
        "selp.b32 %0, 1, 0, p;\n\t}" : "=r"(_d) : "r"(_m), "r"(_p) : "memory"); \
    if (!_d) {                                                                  \
        asm volatile("{\n\t.reg .pred P1;\n\t"                                  \
        "WL_%=:\n\t"                                                            \
        "mbarrier.try_wait.parity.acquire.cta.shared::cta.b64 P1, [%0], %1, 0x989680;\n\t" \
        "@P1 bra.uni WD_%=;\n\t"                                                \
        "bra.uni WL_%=;\n\t"                                                    \
        "WD_%=:\n\t}" :: "r"(_m), "r"(_p) : "memory");                          \
    } } while (0)

__device__ __forceinline__ void ldsm_x4(uint32_t* r, uint32_t addr) {
    asm volatile("ldmatrix.sync.aligned.m8n8.x4.shared.b16 {%0,%1,%2,%3}, [%4];"
                 : "=r"(r[0]), "=r"(r[1]), "=r"(r[2]), "=r"(r[3]) : "r"(addr));
}
__device__ __forceinline__ void mma16816(float* c, const uint32_t* a, uint32_t b0, uint32_t b1) {
    asm volatile("mma.sync.aligned.m16n8k16.row.col.f32.bf16.bf16.f32 "
                 "{%0,%1,%2,%3}, {%4,%5,%6,%7}, {%8,%9}, {%0,%1,%2,%3};"
                 : "+f"(c[0]), "+f"(c[1]), "+f"(c[2]), "+f"(c[3])
                 : "r"(a[0]), "r"(a[1]), "r"(a[2]), "r"(a[3]), "r"(b0), "r"(b1));
}

// ---------------- prep1: W_h* -> g_WB (swzH) and W_hq -> g_GB blocks (swzG) ---
__global__ void __launch_bounds__(256)
prep1(const float* __restrict__ Whq,
      const float* __restrict__ Wi, const float* __restrict__ Wf,
      const float* __restrict__ Wo, const float* __restrict__ Wc) {
    __shared__ float tile[32 * 257];
    const int blk = blockIdx.x;
    const int tid = threadIdx.x;
    if (blk < 1024) {
        const int kt = blk & 15, jt = (blk >> 4) & 15, g = blk >> 8;
        const float* W = (g == 0) ? Wi : (g == 1) ? Wf : (g == 2) ? Wo : Wc;
        for (int i = tid; i < 1024; i += 256) {
            int kk = i >> 5, jj = i & 31;
            tile[kk * 33 + jj] = W[(kt * 32 + kk) * HH + jt * 32 + jj];
        }
        __syncthreads();
        for (int i = tid; i < 1024; i += 256) {
            int jj = i >> 5, kk = i & 31;
            float w = tile[kk * 33 + jj];
            int j   = jt * 32 + jj;
            int cta = j >> 3;
            int row = g * 8 + (j & 7);
            uint32_t offh = (uint32_t)(row * 2048 + (kt * 32 + kk) * 2);
            __nv_bfloat16 hi = __float2bfloat16(w);
            __nv_bfloat16 lo = __float2bfloat16(w - __bfloat162float(hi));
            char* base = g_WB + (size_t)cta * 65536;
            *reinterpret_cast<__nv_bfloat16*>(base + swzH(offh))        = hi;
            *reinterpret_cast<__nv_bfloat16*>(base + swzH(offh + 1024)) = lo;
        }
    } else {
        const int b  = blk - 1024;
        const int kc = b & 31;
        const int nt = b >> 5;
        const bool lo = (kc >= 16);
        const int ksrc = (lo ? (kc - 16) : kc) * 32;
        for (int i = tid; i < 32 * 256; i += 256) {
            int kk = i >> 8, nn = i & 255;
            int n = nt * 256 + nn;
            tile[kk * 257 + nn] = (n < VV) ? Whq[(ksrc + kk) * VV + n] : 0.0f;
        }
        __syncthreads();
        char* blkbase = g_GB + (size_t)(nt * 32 + kc) * 16384;
        for (int c = tid; c < 1024; c += 256) {
            int row = c >> 2, ch = c & 3;
            __nv_bfloat16 v[8];
            #pragma unroll
            for (int i = 0; i < 8; i++) {
                float w = tile[(ch * 8 + i) * 257 + row];
                __nv_bfloat16 hi = __float2bfloat16(w);
                v[i] = lo ? __float2bfloat16(w - __bfloat162float(hi)) : hi;
            }
            uint32_t off = (uint32_t)(row * 64 + ch * 16);
            *reinterpret_cast<int4*>(blkbase + swzG(off)) = *reinterpret_cast<int4*>(v);
        }
    }
}

// ---------------- prep2: x-preacts (bias folded) + state0 -> slot 0 ----------
__global__ void __launch_bounds__(256)
prep2(const int* __restrict__ x, const float* __restrict__ state0,
      const float* __restrict__ Wxi, const float* __restrict__ Wxf,
      const float* __restrict__ Wxo, const float* __restrict__ Wxc,
      const float* __restrict__ bi,  const float* __restrict__ bf_,
      const float* __restrict__ bo,  const float* __restrict__ bc) {
    const int blk = blockIdx.x;
    const int tid = threadIdx.x;
    if (blk < 16384) {
        int idx = blk * 256 + tid;
        int f4  = idx & 7;
        int b   = (idx >> 3) & 63;
        int cta = (idx >> 9) & 63;
        int t   = idx >> 15;
        int col0 = f4 * 4;
        int g  = col0 >> 3;
        int u0 = col0 & 7;
        const float* W  = (g == 0) ? Wxi : (g == 1) ? Wxf : (g == 2) ? Wxo : Wxc;
        const float* bb = (g == 0) ? bi  : (g == 1) ? bf_ : (g == 2) ? bo  : bc;
        int tok = x[b * TT + t];
        float4 w  = *reinterpret_cast<const float4*>(&W[(size_t)tok * HH + cta * 8 + u0]);
        float4 bv = *reinterpret_cast<const float4*>(&bb[cta * 8 + u0]);
        float4 o = {w.x + bv.x, w.y + bv.y, w.z + bv.z, w.w + bv.w};
        *reinterpret_cast<float4*>(&g_XQ[(size_t)idx * 4]) = o;
    } else {
        int idx = (blk - 16384) * 256 + tid;
        if (idx >= BB * 64) return;
        int m = idx >> 6, kp = (idx & 63) * 8;
        const float* src = state0 + (size_t)m * HH + kp;
        float4 f0 = *reinterpret_cast<const float4*>(src);
        float4 f1 = *reinterpret_cast<const float4*>(src + 4);
        float fv[8] = {f0.x, f0.y, f0.z, f0.w, f1.x, f1.y, f1.z, f1.w};
        __nv_bfloat16 hv[8], lv[8];
        #pragma unroll
        for (int i = 0; i < 8; i++) {
            __nv_bfloat16 hi = __float2bfloat16(fv[i]);
            hv[i] = hi;
            lv[i] = __float2bfloat16(fv[i] - __bfloat162float(hi));
        }
        uint32_t off = (uint32_t)(m * 2048 + kp * 2);
        *reinterpret_cast<int4*>(g_A2 + swzH(off))        = *reinterpret_cast<int4*>(hv);
        *reinterpret_cast<int4*>(g_A2 + swzH(off + 1024)) = *reinterpret_cast<int4*>(lv);
    }
}

// ---------------- fused persistent kernel ------------------------------------
#define SM_H   0                // 131072 (rec h: 64 x 2048B swzH)
#define SM_W   131072           // 65536 (rec W)
#define SM_XQ  196608           // 8192
#define SM_P   204800           // 8192
#define SM_C   212992           // 2048
#define SM_TOT 215040

#define GSTAGES 3
#define GA_B 8192
#define GB_B 16384
#define GST_B (GA_B + GB_B)     // 24576 (gemm stages live at smem offset 0)

// one 128x256 output tile; mbarriers pre-initialized; ps[] = cumulative phases
__device__ __forceinline__ void gemm_tile(
    uint32_t sbase, uint32_t bar0, unsigned* ps,
    int mt, int nt, int tid, int wid, int lid,
    const float* __restrict__ bq, float* __restrict__ out)
{
    const int m0 = mt * TM, n0 = nt * TN;
    const int wm = (wid >> 2) * 64, wn = (wid & 3) * 64;
    const int lr = lid & 15,  lc = (lid >> 4) * 16;

    auto akc = [](int kt) { return (kt < 32) ? kt : kt - 32; };
    auto bkc = [](int kt) { return (kt < 16) ? kt : kt - 16; };

    float acc[4][8][4];
    #pragma unroll
    for (int i = 0; i < 4; i++)
        #pragma unroll
        for (int jn = 0; jn < 8; jn++)
            #pragma unroll
            for (int q = 0; q < 4; q++) acc[i][jn][q] = 0.0f;

    if (tid == 0) {
        #pragma unroll
        for (int s = 0; s < GSTAGES; s++) {
            uint32_t b = bar0 + s * 8;
            MBARRIER_EXPECT_TX(b, (uint32_t)GST_B);
            bulk_g2s(sbase + s * GST_B,         g_GA + (size_t)(mt * 32 + akc(s)) * GA_B, GA_B, b);
            bulk_g2s(sbase + s * GST_B + GA_B,  g_GB + (size_t)(nt * 32 + bkc(s)) * GB_B, GB_B, b);
        }
    }

    for (int t = 0; t < KTILES; t++) {
        const int s = t % GSTAGES;
        MBARRIER_WAIT_PARITY(bar0 + s * 8, ps[s] & 1u);
        ps[s]++;

        const uint32_t Ab = sbase + s * GST_B;
        const uint32_t Bb = Ab + GA_B;
        #pragma unroll
        for (int ks2 = 0; ks2 < 2; ks2++) {
            uint32_t af[4][4], bf[4][4];
            #pragma unroll
            for (int i = 0; i < 4; i++)
                ldsm_x4(af[i], Ab + swzG((uint32_t)((wm + i * 16 + lr) * 64 + ks2 * 32 + lc)));
            #pragma unroll
            for (int jn = 0; jn < 4; jn++)
                ldsm_x4(bf[jn], Bb + swzG((uint32_t)((wn + jn * 16 + lr) * 64 + ks2 * 32 + lc)));
            #pragma unroll
            for (int i = 0; i < 4; i++)
                #pragma unroll
                for (int jn = 0; jn < 4; jn++) {
                    mma16816(acc[i][2 * jn],     af[i], bf[jn][0], bf[jn][2]);
                    mma16816(acc[i][2 * jn + 1], af[i], bf[jn][1], bf[jn][3]);
                }
        }
        __syncthreads();
        if (t + GSTAGES < KTILES && tid == 0) {
            int kt = t + GSTAGES;
            uint32_t b = bar0 + s * 8;
            MBARRIER_EXPECT_TX(b, (uint32_t)GST_B);
            bulk_g2s(sbase + s * GST_B,        g_GA + (size_t)(mt * 32 + akc(kt)) * GA_B, GA_B, b);
            bulk_g2s(sbase + s * GST_B + GA_B, g_GB + (size_t)(nt * 32 + bkc(kt)) * GB_B, GB_B, b);
        }
    }

    const int qr = lid >> 2;
    const int qc = (lid & 3) * 2;
    #pragma unroll
    for (int i = 0; i < 4; i++) {
        int mrow = m0 + wm + i * 16 + qr;
        #pragma unroll
        for (int jn = 0; jn < 8; jn++) {
            int n = n0 + wn + jn * 8 + qc;
            if (n < VV) {
                float bx = bq[n], by = bq[n + 1 < VV ? n + 1 : n];
                float2 v0 = {acc[i][jn][0] + bx, acc[i][jn][1] + by};
                float2 v1 = {acc[i][jn][2] + bx, acc[i][jn][3] + by};
                *reinterpret_cast<float2*>(out + (size_t)mrow * VV + n) = v0;
                *reinterpret_cast<float2*>(out + (size_t)(mrow + 8) * VV + n) = v1;
            }
        }
    }
}

__global__ void __launch_bounds__(256, 1)
lstm_fused(const float* __restrict__ cell0, const float* __restrict__ bq,
           float* __restrict__ out) {
    extern __shared__ __align__(128) char sm[];
    __shared__ __align__(8) uint64_t s_bar;          // rec bulk barrier
    __shared__ __align__(8) uint64_t s_gbar[GSTAGES];
    __shared__ unsigned s_base;
    const uint32_t hbase = smem_u32(sm);
    const uint32_t bar   = smem_u32(&s_bar);
    const uint32_t gbar0 = smem_u32(&s_gbar[0]);

    const int tid = threadIdx.x;
    const int wid = tid >> 5;
    const int lid = tid & 31;
    const int cta = blockIdx.x;

    // barriers init
    if (tid == 0) {
        MBARRIER_INIT(bar, 1);
        for (int s = 0; s < GSTAGES; s++) MBARRIER_INIT(gbar0 + s * 8, 1);
    }
    __syncthreads();

    // ---- start barrier: all 148 CTAs capture the same g_gen base ----
    if (tid == 0) {
        unsigned b = *(volatile unsigned*)&g_gen;
        s_base = b;
        __threadfence();
        unsigned arr = atomicAdd(&g_cnt0, 1u);
        if (arr == ALL_CTAS - 1) {
            atomicExch(&g_cnt0, 0u);
            __threadfence();
            atomicAdd(&g_gen, 1u);
        }
        while ((*(volatile unsigned*)&g_gen) - b < 1u) __nanosleep(40);
    }
    __syncthreads();
    const unsigned base = s_base;
    unsigned ps[GSTAGES] = {0, 0, 0};

    if (cta < REC_CTAS) {
        // ================= recurrence (CTAs 0..63) =================
        const uint32_t wbase = hbase + SM_W;
        const uint32_t xqb   = hbase + SM_XQ;
        float* pbuf  = reinterpret_cast<float*>(sm + SM_P);
        float* cellb = reinterpret_cast<float*>(sm + SM_C);
        float* sxq   = reinterpret_cast<float*>(sm + SM_XQ);

        const int j0  = cta * 8;
        const int mg  = wid >> 1;
        const int ng  = wid & 1;
        const int lr  = lid & 15;
        const int lc  = (lid >> 4) * 16;
        const int eb  = tid >> 2;
        const int u0  = (tid & 3) * 2;
        const int j   = j0 + u0;

        // pin weights
        {
            const char* src = g_WB + (size_t)cta * 65536;
            for (int c = tid; c < 4096; c += 256)
                cp_async16(wbase + c * 16, src + (size_t)c * 16);
            asm volatile("cp.async.commit_group;" ::: "memory");
        }
        for (int i = tid; i < 512; i += 256)
            cellb[i] = cell0[(size_t)(i >> 3) * HH + j0 + (i & 7)];
        asm volatile("cp.async.wait_group 0;" ::: "memory");
        __syncthreads();

        const uint32_t rowA = (uint32_t)((mg * 16 + lr) * 2048);
        const uint32_t rowW = (uint32_t)((ng * 16 + lr) * 2048);

        for (int t = 0; t < TT; t++) {
            if (tid == 0) {
                MBARRIER_EXPECT_TX(bar, 131072u + 8192u);
                bulk_g2s(hbase, g_A2 + (size_t)t * 131072, 131072u, bar);
                bulk_g2s(xqb, (const char*)g_XQ + ((size_t)(t * 64 + cta)) * 8192, 8192u, bar);
            }
            MBARRIER_WAIT_PARITY(bar, (uint32_t)(t & 1));
            __syncthreads();

            float acc0[4] = {0.f, 0.f, 0.f, 0.f};
            float acc1[4] = {0.f, 0.f, 0.f, 0.f};
            #pragma unroll 4
            for (int kt = 0; kt < 32; kt++) {
                uint32_t ahi[4], alo[4], bhi[4], blo[4];
                uint32_t ca = rowA + kt * 32 + lc;
                uint32_t cw = rowW + kt * 32 + lc;
                ldsm_x4(ahi, hbase + swzH(ca));
                ldsm_x4(alo, hbase + swzH(ca + 1024));
                ldsm_x4(bhi, wbase + swzH(cw));
                ldsm_x4(blo, wbase + swzH(cw + 1024));
                mma16816(acc0, ahi, bhi[0], bhi[2]);
                mma16816(acc1, ahi, bhi[1], bhi[3]);
                mma16816(acc0, alo, bhi[0], bhi[2]);
                mma16816(acc1, alo, bhi[1], bhi[3]);
                mma16816(acc0, ahi, blo[0], blo[2]);
                mma16816(acc1, ahi, blo[1], blo[3]);
            }

            {
                const int qr = lid >> 2;
                const int qc = (lid & 3) * 2;
                int row = mg * 16 + qr;
                int col = ng * 16 + qc;
                pbuf[row * 32 + col]           = acc0[0];
                pbuf[row * 32 + col + 1]       = acc0[1];
                pbuf[(row + 8) * 32 + col]     = acc0[2];
                pbuf[(row + 8) * 32 + col + 1] = acc0[3];
                pbuf[row * 32 + col + 8]       = acc1[0];
                pbuf[row * 32 + col + 9]       = acc1[1];
                pbuf[(row + 8) * 32 + col + 8] = acc1[2];
                pbuf[(row + 8) * 32 + col + 9] = acc1[3];
            }
            __syncthreads();

            {
                const float* pr = pbuf + eb * 32;
                const float* xr = sxq  + eb * 32;
                float i0 = sigmoidf_(pr[u0]          + xr[u0]);
                float i1 = sigmoidf_(pr[u0 + 1]      + xr[u0 + 1]);
                float f0 = sigmoidf_(pr[8 + u0]      + xr[8 + u0]);
                float f1 = sigmoidf_(pr[8 + u0 + 1]  + xr[8 + u0 + 1]);
                float o0 = sigmoidf_(pr[16 + u0]     + xr[16 + u0]);
                float o1 = sigmoidf_(pr[16 + u0 + 1] + xr[16 + u0 + 1]);
                float g0 = tanhf    (pr[24 + u0]     + xr[24 + u0]);
                float g1 = tanhf    (pr[24 + u0 + 1] + xr[24 + u0 + 1]);

                float c0 = cellb[eb * 8 + u0];
                float c1 = cellb[eb * 8 + u0 + 1];
                float cn0 = fmaf(f0, c0, i0 * g0);
                float cn1 = fmaf(f1, c1, i1 * g1);
                cellb[eb * 8 + u0]     = cn0;
                cellb[eb * 8 + u0 + 1] = cn1;
                float hn0 = o0 * tanhf(cn0);
                float hn1 = o1 * tanhf(cn1);

                __nv_bfloat16 h0 = __float2bfloat16(hn0);
                __nv_bfloat16 h1 = __float2bfloat16(hn1);
                __nv_bfloat16 l0 = __float2bfloat16(hn0 - __bfloat162float(h0));
                __nv_bfloat16 l1 = __float2bfloat16(hn1 - __bfloat162float(h1));
                uint32_t hib = (uint32_t)__bfloat16_as_ushort(h0) |
                               ((uint32_t)__bfloat16_as_ushort(h1) << 16);
                uint32_t lob = (uint32_t)__bfloat16_as_ushort(l0) |
                               ((uint32_t)__bfloat16_as_ushort(l1) << 16);
                char* dst = g_A2 + (size_t)(t + 1) * 131072;
                uint32_t offh = (uint32_t)(eb * 2048 + j * 2);
                *reinterpret_cast<uint32_t*>(dst + swzH(offh))        = hib;
                *reinterpret_cast<uint32_t*>(dst + swzH(offh + 1024)) = lob;
                int mt  = t >> 1;
                int row = ((t & 1) << 6) | eb;
                int kcH = j >> 5;
                uint32_t offg = (uint32_t)(row * 64 + ((j & 31) * 2));
                char* ga  = g_GA + (size_t)(mt * 32 + kcH) * GA_B;
                char* gal = g_GA + (size_t)(mt * 32 + 16 + kcH) * GA_B;
                *reinterpret_cast<uint32_t*>(ga  + swzG(offg)) = hib;
                *reinterpret_cast<uint32_t*>(gal + swzG(offg)) = lob;
                if (t == TT - 1) {
                    float2 hv = {hn0, hn1};
                    *reinterpret_cast<float2*>(out + OUT_STATE_OFF + (size_t)eb * HH + j) = hv;
                }
            }
            __threadfence();
            __syncthreads();

            // rec step barrier (64 CTAs); winner bumps g_gen (every step)
            if (tid == 0) {
                unsigned arr = atomicAdd(&g_cnt, 1u);
                if (arr == REC_CTAS - 1) {
                    atomicExch(&g_cnt, 0u);
                    __threadfence();
                    atomicAdd(&g_gen, 1u);
                } else if (t < TT - 1) {
                    while ((*(volatile unsigned*)&g_gen) - base < (unsigned)(t + 2))
                        __nanosleep(40);
                }
                __threadfence();
            }
            __syncthreads();
        }

        for (int i = tid; i < 512; i += 256)
            out[OUT_CELL_OFF + (size_t)(i >> 3) * HH + j0 + (i & 7)] = cellb[i];
        __syncthreads();

        // ---- tail: 4 gemm tiles per rec CTA ----
        for (int q = SPLIT_Q + cta * 4; q < SPLIT_Q + cta * 4 + 4; q++) {
            int mt = q / NTILES, nt = q % NTILES;
            if (tid == 0) {
                while ((*(volatile unsigned*)&g_gen) - base < (unsigned)(2 * mt + 3))
                    __nanosleep(100);
                __threadfence();
            }
            __syncthreads();
            gemm_tile(hbase, gbar0, ps, mt, nt, tid, wid, lid, bq, out);
        }
    } else {
        // ================= gemm workers (CTAs 64..147) =================
        for (int q = cta - REC_CTAS; q < SPLIT_Q; q += GEMM_CTAS) {
            int mt = q / NTILES, nt = q % NTILES;
            if (tid == 0) {
                while ((*(volatile unsigned*)&g_gen) - base < (unsigned)(2 * mt + 3))
                    __nanosleep(100);
                __threadfence();
            }
            __syncthreads();
            gemm_tile(hbase, gbar0, ps, mt, nt, tid, wid, lid, bq, out);
        }
    }
}

// ---------------- launch ----------------
extern "C" void kernel_launch(void* const* d_in, const int* in_sizes, int n_in,
                              void* d_out, int out_size) {
    const int*   x     = (const int*)  d_in[0];
    const float* state = (const float*)d_in[1];
    const float* cell  = (const float*)d_in[2];
    const float* W_xi  = (const float*)d_in[3];
    const float* W_hi  = (const float*)d_in[4];
    const float* b_i   = (const float*)d_in[5];
    const float* W_xf  = (const float*)d_in[6];
    const float* W_hf  = (const float*)d_in[7];
    const float* b_f   = (const float*)d_in[8];
    const float* W_xo  = (const float*)d_in[9];
    const float* W_ho  = (const float*)d_in[10];
    const float* b_o   = (const float*)d_in[11];
    const float* W_xc  = (const float*)d_in[12];
    const float* W_hc  = (const float*)d_in[13];
    const float* b_c   = (const float*)d_in[14];
    const float* W_hq  = (const float*)d_in[15];
    const float* b_q   = (const float*)d_in[16];
    float* out = (float*)d_out;

    cudaFuncSetAttribute(lstm_fused, cudaFuncAttributeMaxDynamicSharedMemorySize, SM_TOT);

    prep1<<<1024 + 32 * NTILES, 256>>>(W_hq, W_hi, W_hf, W_ho, W_hc);
    prep2<<<16384 + 16, 256>>>(x, state, W_xi, W_xf, W_xo, W_xc,
                               b_i, b_f, b_o, b_c);
    lstm_fused<<<ALL_CTAS, 256, SM_TOT>>>(cell, b_q, out);
}

// round 11
// speedup vs baseline: 1.5471x; 1.0649x over previous
#include <cuda_runtime.h>
#include <cuda_bf16.h>
#include <cstdint>

// ---------------- problem constants ----------------
#define TT   128
#define BB   64
#define HH   512
#define VV   10000

#define KTILES 48            // logical K' = 1536 in 32-elem tiles
#define MTILES 64            // 8192 / 128
#define NTILES 40            // 40*256 = 10240
#define TM     128
#define TN     256
#define QTOTAL (MTILES * NTILES)   // 2560

#define REC_CTAS  64
#define ALL_CTAS  148

#define OUT_STATE_OFF 81920000u
#define OUT_CELL_OFF  81952768u

// swizzles: swzH for 2048B rows (rec h/W tiles), swzG for 64B rows (gemm blocks)
__device__ __forceinline__ uint32_t swzH(uint32_t off) { return off ^ (((off >> 11) & 7u) << 4); }
__device__ __forceinline__ uint32_t swzG(uint32_t off) { return off ^ ((off >> 3) & 0x30u); }

// ---------------- device scratch ----------------
__device__ __align__(16) char  g_A2[(size_t)(TT + 1) * BB * 2048];   // h slots, swzH rows
__device__ __align__(16) char  g_GA[(size_t)MTILES * 32 * 8192];     // gemm A blocks, swzG
__device__ __align__(16) char  g_GB[(size_t)NTILES * 32 * 16384];    // gemm B blocks, swzG
__device__ __align__(16) char  g_WB[(size_t)64 * 65536];             // rec W regions, swzH
__device__ __align__(16) float g_XQ[(size_t)TT * BB * 2048];         // x-preact (bias folded)
__device__ unsigned g_cnt  = 0;   // rec step barrier counter (64)
__device__ unsigned g_cnt0 = 0;   // start barrier counter (148)
__device__ unsigned g_gen  = 0;   // monotonic progress counter
__device__ unsigned g_tq   = 0;   // tile work queue head (reset at start barrier)

__device__ __forceinline__ float sigmoidf_(float x) { return 1.0f / (1.0f + expf(-x)); }

__device__ __forceinline__ uint32_t smem_u32(const void* p) {
    uint32_t a;
    asm("{ .reg .u64 t; cvta.to.shared.u64 t, %1; cvt.u32.u64 %0, t; }" : "=r"(a) : "l"(p));
    return a;
}
__device__ __forceinline__ void cp_async16(uint32_t dst, const void* src) {
    asm volatile("cp.async.cg.shared.global [%0], [%1], 16;" :: "r"(dst), "l"(src));
}
__device__ __forceinline__ void bulk_g2s(uint32_t dst, const void* src, uint32_t bytes, uint32_t mbar) {
    asm volatile("cp.async.bulk.shared::cluster.global.mbarrier::complete_tx::bytes "
                 "[%0], [%1], %2, [%3];"
                 :: "r"(dst), "l"(src), "r"(bytes), "r"(mbar) : "memory");
}
#define MBARRIER_INIT(addr, cnt) \
    asm volatile("mbarrier.init.shared.b64 [%0], %1;" :: "r"(addr), "r"(cnt) : "memory")
#define MBARRIER_EXPECT_TX(addr, tx) \
    asm volatile("mbarrier.arrive.expect_tx.shared.b64 _, [%0], %1;" :: "r"(addr), "r"(tx) : "memory")
#define MBARRIER_WAIT_PARITY(mbar, par) do {                                    \
    uint32_t _m = (mbar); uint32_t _p = (par); uint32_t _d;                     \
    asm volatile("{\n\t.reg .pred p;\n\t"                                       \
        "mbarrier.try_wait.parity.acquire.cta.shared::cta.b64 p, [%1], %2;\n\t" \
        "selp.b32 %0, 1, 0, p;\n\t}" : "=r"(_d) : "r"(_m), "r"(_p) : "memory"); \
    if (!_d) {                                                                  \
        asm volatile("{\n\t.reg .pred P1;\n\t"                                  \
        "WL_%=:\n\t"                                                            \
        "mbarrier.try_wait.parity.acquire.cta.shared::cta.b64 P1, [%0], %1, 0x989680;\n\t" \
        "@P1 bra.uni WD_%=;\n\t"                                                \
        "bra.uni WL_%=;\n\t"                                                    \
        "WD_%=:\n\t}" :: "r"(_m), "r"(_p) : "memory");                          \
    } } while (0)

__device__ __forceinline__ void ldsm_x4(uint32_t* r, uint32_t addr) {
    asm volatile("ldmatrix.sync.aligned.m8n8.x4.shared.b16 {%0,%1,%2,%3}, [%4];"
                 : "=r"(r[0]), "=r"(r[1]), "=r"(r[2]), "=r"(r[3]) : "r"(addr));
}
__device__ __forceinline__ void mma16816(float* c, const uint32_t* a, uint32_t b0, uint32_t b1) {
    asm volatile("mma.sync.aligned.m16n8k16.row.col.f32.bf16.bf16.f32 "
                 "{%0,%1,%2,%3}, {%4,%5,%6,%7}, {%8,%9}, {%0,%1,%2,%3};"
                 : "+f"(c[0]), "+f"(c[1]), "+f"(c[2]), "+f"(c[3])
                 : "r"(a[0]), "r"(a[1]), "r"(a[2]), "r"(a[3]), "r"(b0), "r"(b1));
}

// ---------------- prep1: W_h* -> g_WB (swzH) and W_hq -> g_GB blocks (swzG) ---
__global__ void __launch_bounds__(256)
prep1(const float* __restrict__ Whq,
      const float* __restrict__ Wi, const float* __restrict__ Wf,
      const float* __restrict__ Wo, const float* __restrict__ Wc) {
    __shared__ float tile[32 * 257];
    const int blk = blockIdx.x;
    const int tid = threadIdx.x;
    if (blk < 1024) {
        const int kt = blk & 15, jt = (blk >> 4) & 15, g = blk >> 8;
        const float* W = (g == 0) ? Wi : (g == 1) ? Wf : (g == 2) ? Wo : Wc;
        for (int i = tid; i < 1024; i += 256) {
            int kk = i >> 5, jj = i & 31;
            tile[kk * 33 + jj] = W[(kt * 32 + kk) * HH + jt * 32 + jj];
        }
        __syncthreads();
        for (int i = tid; i < 1024; i += 256) {
            int jj = i >> 5, kk = i & 31;
            float w = tile[kk * 33 + jj];
            int j   = jt * 32 + jj;
            int cta = j >> 3;
            int row = g * 8 + (j & 7);
            uint32_t offh = (uint32_t)(row * 2048 + (kt * 32 + kk) * 2);
            __nv_bfloat16 hi = __float2bfloat16(w);
            __nv_bfloat16 lo = __float2bfloat16(w - __bfloat162float(hi));
            char* base = g_WB + (size_t)cta * 65536;
            *reinterpret_cast<__nv_bfloat16*>(base + swzH(offh))        = hi;
            *reinterpret_cast<__nv_bfloat16*>(base + swzH(offh + 1024)) = lo;
        }
    } else {
        const int b  = blk - 1024;
        const int kc = b & 31;
        const int nt = b >> 5;
        const bool lo = (kc >= 16);
        const int ksrc = (lo ? (kc - 16) : kc) * 32;
        for (int i = tid; i < 32 * 256; i += 256) {
            int kk = i >> 8, nn = i & 255;
            int n = nt * 256 + nn;
            tile[kk * 257 + nn] = (n < VV) ? Whq[(ksrc + kk) * VV + n] : 0.0f;
        }
        __syncthreads();
        char* blkbase = g_GB + (size_t)(nt * 32 + kc) * 16384;
        for (int c = tid; c < 1024; c += 256) {
            int row = c >> 2, ch = c & 3;
            __nv_bfloat16 v[8];
            #pragma unroll
            for (int i = 0; i < 8; i++) {
                float w = tile[(ch * 8 + i) * 257 + row];
                __nv_bfloat16 hi = __float2bfloat16(w);
                v[i] = lo ? __float2bfloat16(w - __bfloat162float(hi)) : hi;
            }
            uint32_t off = (uint32_t)(row * 64 + ch * 16);
            *reinterpret_cast<int4*>(blkbase + swzG(off)) = *reinterpret_cast<int4*>(v);
        }
    }
}

// ---------------- prep2: x-preacts (bias folded) + state0 -> slot 0 ----------
__global__ void __launch_bounds__(256)
prep2(const int* __restrict__ x, const float* __restrict__ state0,
      const float* __restrict__ Wxi, const float* __restrict__ Wxf,
      const float* __restrict__ Wxo, const float* __restrict__ Wxc,
      const float* __restrict__ bi,  const float* __restrict__ bf_,
      const float* __restrict__ bo,  const float* __restrict__ bc) {
    const int blk = blockIdx.x;
    const int tid = threadIdx.x;
    if (blk < 16384) {
        int idx = blk * 256 + tid;
        int f4  = idx & 7;
        int b   = (idx >> 3) & 63;
        int cta = (idx >> 9) & 63;
        int t   = idx >> 15;
        int col0 = f4 * 4;
        int g  = col0 >> 3;
        int u0 = col0 & 7;
        const float* W  = (g == 0) ? Wxi : (g == 1) ? Wxf : (g == 2) ? Wxo : Wxc;
        const float* bb = (g == 0) ? bi  : (g == 1) ? bf_ : (g == 2) ? bo  : bc;
        int tok = x[b * TT + t];
        float4 w  = *reinterpret_cast<const float4*>(&W[(size_t)tok * HH + cta * 8 + u0]);
        float4 bv = *reinterpret_cast<const float4*>(&bb[cta * 8 + u0]);
        float4 o = {w.x + bv.x, w.y + bv.y, w.z + bv.z, w.w + bv.w};
        *reinterpret_cast<float4*>(&g_XQ[(size_t)idx * 4]) = o;
    } else {
        int idx = (blk - 16384) * 256 + tid;
        if (idx >= BB * 64) return;
        int m = idx >> 6, kp = (idx & 63) * 8;
        const float* src = state0 + (size_t)m * HH + kp;
        float4 f0 = *reinterpret_cast<const float4*>(src);
        float4 f1 = *reinterpret_cast<const float4*>(src + 4);
        float fv[8] = {f0.x, f0.y, f0.z, f0.w, f1.x, f1.y, f1.z, f1.w};
        __nv_bfloat16 hv[8], lv[8];
        #pragma unroll
        for (int i = 0; i < 8; i++) {
            __nv_bfloat16 hi = __float2bfloat16(fv[i]);
            hv[i] = hi;
            lv[i] = __float2bfloat16(fv[i] - __bfloat162float(hi));
        }
        uint32_t off = (uint32_t)(m * 2048 + kp * 2);
        *reinterpret_cast<int4*>(g_A2 + swzH(off))        = *reinterpret_cast<int4*>(hv);
        *reinterpret_cast<int4*>(g_A2 + swzH(off + 1024)) = *reinterpret_cast<int4*>(lv);
    }
}

// ---------------- fused persistent kernel ------------------------------------
#define SM_H   0                // 131072 (rec h: 64 x 2048B swzH)
#define SM_W   131072           // 65536 (rec W)
#define SM_XQ  196608           // 8192
#define SM_P   204800           // 8192
#define SM_C   212992           // 2048
#define SM_TOT 215040

#define GSTAGES 3
#define GA_B 8192
#define GB_B 16384
#define GST_B (GA_B + GB_B)     // 24576 (gemm stages live at smem offset 0)

// one 128x256 output tile; barriers pre-initialized; ps[] = cumulative phases
__device__ __forceinline__ void gemm_tile(
    uint32_t sbase, uint32_t bar0, unsigned* ps,
    int mt, int nt, int tid, int wid, int lid,
    const float* __restrict__ bq, float* __restrict__ out)
{
    const int m0 = mt * TM, n0 = nt * TN;
    const int wm = (wid >> 2) * 64, wn = (wid & 3) * 64;
    const int lr = lid & 15,  lc = (lid >> 4) * 16;

    auto akc = [](int kt) { return (kt < 32) ? kt : kt - 32; };
    auto bkc = [](int kt) { return (kt < 16) ? kt : kt - 16; };

    float acc[4][8][4];
    #pragma unroll
    for (int i = 0; i < 4; i++)
        #pragma unroll
        for (int jn = 0; jn < 8; jn++)
            #pragma unroll
            for (int q = 0; q < 4; q++) acc[i][jn][q] = 0.0f;

    if (tid == 0) {
        #pragma unroll
        for (int s = 0; s < GSTAGES; s++) {
            uint32_t b = bar0 + s * 8;
            MBARRIER_EXPECT_TX(b, (uint32_t)GST_B);
            bulk_g2s(sbase + s * GST_B,         g_GA + (size_t)(mt * 32 + akc(s)) * GA_B, GA_B, b);
            bulk_g2s(sbase + s * GST_B + GA_B,  g_GB + (size_t)(nt * 32 + bkc(s)) * GB_B, GB_B, b);
        }
    }

    for (int t = 0; t < KTILES; t++) {
        const int s = t % GSTAGES;
        MBARRIER_WAIT_PARITY(bar0 + s * 8, ps[s] & 1u);
        ps[s]++;

        const uint32_t Ab = sbase + s * GST_B;
        const uint32_t Bb = Ab + GA_B;
        // batch ALL 16 ldsm first (both ks2 halves), then 128 mma
        uint32_t af[2][4][4], bf[2][4][4];
        #pragma unroll
        for (int ks2 = 0; ks2 < 2; ks2++) {
            #pragma unroll
            for (int i = 0; i < 4; i++)
                ldsm_x4(af[ks2][i], Ab + swzG((uint32_t)((wm + i * 16 + lr) * 64 + ks2 * 32 + lc)));
            #pragma unroll
            for (int jn = 0; jn < 4; jn++)
                ldsm_x4(bf[ks2][jn], Bb + swzG((uint32_t)((wn + jn * 16 + lr) * 64 + ks2 * 32 + lc)));
        }
        #pragma unroll
        for (int ks2 = 0; ks2 < 2; ks2++)
            #pragma unroll
            for (int i = 0; i < 4; i++)
                #pragma unroll
                for (int jn = 0; jn < 4; jn++) {
                    mma16816(acc[i][2 * jn],     af[ks2][i], bf[ks2][jn][0], bf[ks2][jn][2]);
                    mma16816(acc[i][2 * jn + 1], af[ks2][i], bf[ks2][jn][1], bf[ks2][jn][3]);
                }
        __syncthreads();
        if (t + GSTAGES < KTILES && tid == 0) {
            int kt = t + GSTAGES;
            uint32_t b = bar0 + s * 8;
            MBARRIER_EXPECT_TX(b, (uint32_t)GST_B);
            bulk_g2s(sbase + s * GST_B,        g_GA + (size_t)(mt * 32 + akc(kt)) * GA_B, GA_B, b);
            bulk_g2s(sbase + s * GST_B + GA_B, g_GB + (size_t)(nt * 32 + bkc(kt)) * GB_B, GB_B, b);
        }
    }

    const int qr = lid >> 2;
    const int qc = (lid & 3) * 2;
    #pragma unroll
    for (int i = 0; i < 4; i++) {
        int mrow = m0 + wm + i * 16 + qr;
        #pragma unroll
        for (int jn = 0; jn < 8; jn++) {
            int n = n0 + wn + jn * 8 + qc;
            if (n < VV) {
                float bx = bq[n], by = bq[n + 1 < VV ? n + 1 : n];
                float2 v0 = {acc[i][jn][0] + bx, acc[i][jn][1] + by};
                float2 v1 = {acc[i][jn][2] + bx, acc[i][jn][3] + by};
                *reinterpret_cast<float2*>(out + (size_t)mrow * VV + n) = v0;
                *reinterpret_cast<float2*>(out + (size_t)(mrow + 8) * VV + n) = v1;
            }
        }
    }
}

// claim + (gated) run tiles from the shared queue until exhausted
__device__ __forceinline__ void gemm_drain(
    uint32_t sbase, uint32_t bar0, unsigned* ps, unsigned base,
    int tid, int wid, int lid, unsigned* s_q,
    const float* __restrict__ bq, float* __restrict__ out)
{
    for (;;) {
        if (tid == 0) *s_q = atomicAdd(&g_tq, 1u);
        __syncthreads();
        unsigned q = *s_q;
        __syncthreads();
        if (q >= QTOTAL) break;
        int mt = (int)(q / NTILES), nt = (int)(q % NTILES);
        if (tid == 0) {
            while ((*(volatile unsigned*)&g_gen) - base < (unsigned)(2 * mt + 3))
                __nanosleep(100);
            __threadfence();
        }
        __syncthreads();
        gemm_tile(sbase, bar0, ps, mt, nt, tid, wid, lid, bq, out);
    }
}

__global__ void __launch_bounds__(256, 1)
lstm_fused(const float* __restrict__ cell0, const float* __restrict__ bq,
           float* __restrict__ out) {
    extern __shared__ __align__(128) char sm[];
    __shared__ __align__(8) uint64_t s_bar;          // rec bulk barrier
    __shared__ __align__(8) uint64_t s_gbar[GSTAGES];
    __shared__ unsigned s_base;
    __shared__ unsigned s_q;
    const uint32_t hbase = smem_u32(sm);
    const uint32_t bar   = smem_u32(&s_bar);
    const uint32_t gbar0 = smem_u32(&s_gbar[0]);

    const int tid = threadIdx.x;
    const int wid = tid >> 5;
    const int lid = tid & 31;
    const int cta = blockIdx.x;

    if (tid == 0) {
        MBARRIER_INIT(bar, 1);
        for (int s = 0; s < GSTAGES; s++) MBARRIER_INIT(gbar0 + s * 8, 1);
    }
    __syncthreads();

    // ---- start barrier: capture g_gen base; CTA0 resets the tile queue ----
    if (tid == 0) {
        unsigned b = *(volatile unsigned*)&g_gen;
        s_base = b;
        if (cta == 0) atomicExch(&g_tq, 0u);
        __threadfence();
        unsigned arr = atomicAdd(&g_cnt0, 1u);
        if (arr == ALL_CTAS - 1) {
            atomicExch(&g_cnt0, 0u);
            __threadfence();
            atomicAdd(&g_gen, 1u);
        }
        while ((*(volatile unsigned*)&g_gen) - b < 1u) __nanosleep(40);
    }
    __syncthreads();
    const unsigned base = s_base;
    unsigned ps[GSTAGES] = {0, 0, 0};

    if (cta < REC_CTAS) {
        // ================= recurrence (CTAs 0..63) =================
        const uint32_t wbase = hbase + SM_W;
        const uint32_t xqb   = hbase + SM_XQ;
        float* pbuf  = reinterpret_cast<float*>(sm + SM_P);
        float* cellb = reinterpret_cast<float*>(sm + SM_C);
        float* sxq   = reinterpret_cast<float*>(sm + SM_XQ);

        const int j0  = cta * 8;
        const int mg  = wid >> 1;
        const int ng  = wid & 1;
        const int lr  = lid & 15;
        const int lc  = (lid >> 4) * 16;
        const int eb  = tid >> 2;
        const int u0  = (tid & 3) * 2;
        const int j   = j0 + u0;

        {
            const char* src = g_WB + (size_t)cta * 65536;
            for (int c = tid; c < 4096; c += 256)
                cp_async16(wbase + c * 16, src + (size_t)c * 16);
            asm volatile("cp.async.commit_group;" ::: "memory");
        }
        for (int i = tid; i < 512; i += 256)
            cellb[i] = cell0[(size_t)(i >> 3) * HH + j0 + (i & 7)];
        asm volatile("cp.async.wait_group 0;" ::: "memory");
        __syncthreads();

        const uint32_t rowA = (uint32_t)((mg * 16 + lr) * 2048);
        const uint32_t rowW = (uint32_t)((ng * 16 + lr) * 2048);

        for (int t = 0; t < TT; t++) {
            if (tid == 0) {
                MBARRIER_EXPECT_TX(bar, 131072u + 8192u);
                bulk_g2s(hbase, g_A2 + (size_t)t * 131072, 131072u, bar);
                bulk_g2s(xqb, (const char*)g_XQ + ((size_t)(t * 64 + cta)) * 8192, 8192u, bar);
            }
            MBARRIER_WAIT_PARITY(bar, (uint32_t)(t & 1));
            __syncthreads();

            float acc0[4] = {0.f, 0.f, 0.f, 0.f};
            float acc1[4] = {0.f, 0.f, 0.f, 0.f};
            #pragma unroll 4
            for (int kt = 0; kt < 32; kt++) {
                uint32_t ahi[4], alo[4], bhi[4], blo[4];
                uint32_t ca = rowA + kt * 32 + lc;
                uint32_t cw = rowW + kt * 32 + lc;
                ldsm_x4(ahi, hbase + swzH(ca));
                ldsm_x4(alo, hbase + swzH(ca + 1024));
                ldsm_x4(bhi, wbase + swzH(cw));
                ldsm_x4(blo, wbase + swzH(cw + 1024));
                mma16816(acc0, ahi, bhi[0], bhi[2]);
                mma16816(acc1, ahi, bhi[1], bhi[3]);
                mma16816(acc0, alo, bhi[0], bhi[2]);
                mma16816(acc1, alo, bhi[1], bhi[3]);
                mma16816(acc0, ahi, blo[0], blo[2]);
                mma16816(acc1, ahi, blo[1], blo[3]);
            }

            {
                const int qr = lid >> 2;
                const int qc = (lid & 3) * 2;
                int row = mg * 16 + qr;
                int col = ng * 16 + qc;
                pbuf[row * 32 + col]           = acc0[0];
                pbuf[row * 32 + col + 1]       = acc0[1];
                pbuf[(row + 8) * 32 + col]     = acc0[2];
                pbuf[(row + 8) * 32 + col + 1] = acc0[3];
                pbuf[row * 32 + col + 8]       = acc1[0];
                pbuf[row * 32 + col + 9]       = acc1[1];
                pbuf[(row + 8) * 32 + col + 8] = acc1[2];
                pbuf[(row + 8) * 32 + col + 9] = acc1[3];
            }
            __syncthreads();

            {
                const float* pr = pbuf + eb * 32;
                const float* xr = sxq  + eb * 32;
                float i0 = sigmoidf_(pr[u0]          + xr[u0]);
                float i1 = sigmoidf_(pr[u0 + 1]      + xr[u0 + 1]);
                float f0 = sigmoidf_(pr[8 + u0]      + xr[8 + u0]);
                float f1 = sigmoidf_(pr[8 + u0 + 1]  + xr[8 + u0 + 1]);
                float o0 = sigmoidf_(pr[16 + u0]     + xr[16 + u0]);
                float o1 = sigmoidf_(pr[16 + u0 + 1] + xr[16 + u0 + 1]);
                float g0 = tanhf    (pr[24 + u0]     + xr[24 + u0]);
                float g1 = tanhf    (pr[24 + u0 + 1] + xr[24 + u0 + 1]);

                float c0 = cellb[eb * 8 + u0];
                float c1 = cellb[eb * 8 + u0 + 1];
                float cn0 = fmaf(f0, c0, i0 * g0);
                float cn1 = fmaf(f1, c1, i1 * g1);
                cellb[eb * 8 + u0]     = cn0;
                cellb[eb * 8 + u0 + 1] = cn1;
                float hn0 = o0 * tanhf(cn0);
                float hn1 = o1 * tanhf(cn1);

                __nv_bfloat16 h0 = __float2bfloat16(hn0);
                __nv_bfloat16 h1 = __float2bfloat16(hn1);
                __nv_bfloat16 l0 = __float2bfloat16(hn0 - __bfloat162float(h0));
                __nv_bfloat16 l1 = __float2bfloat16(hn1 - __bfloat162float(h1));
                uint32_t hib = (uint32_t)__bfloat16_as_ushort(h0) |
                               ((uint32_t)__bfloat16_as_ushort(h1) << 16);
                uint32_t lob = (uint32_t)__bfloat16_as_ushort(l0) |
                               ((uint32_t)__bfloat16_as_ushort(l1) << 16);
                char* dst = g_A2 + (size_t)(t + 1) * 131072;
                uint32_t offh = (uint32_t)(eb * 2048 + j * 2);
                *reinterpret_cast<uint32_t*>(dst + swzH(offh))        = hib;
                *reinterpret_cast<uint32_t*>(dst + swzH(offh + 1024)) = lob;
                int mt  = t >> 1;
                int row = ((t & 1) << 6) | eb;
                int kcH = j >> 5;
                uint32_t offg = (uint32_t)(row * 64 + ((j & 31) * 2));
                char* ga  = g_GA + (size_t)(mt * 32 + kcH) * GA_B;
                char* gal = g_GA + (size_t)(mt * 32 + 16 + kcH) * GA_B;
                *reinterpret_cast<uint32_t*>(ga  + swzG(offg)) = hib;
                *reinterpret_cast<uint32_t*>(gal + swzG(offg)) = lob;
                if (t == TT - 1) {
                    float2 hv = {hn0, hn1};
                    *reinterpret_cast<float2*>(out + OUT_STATE_OFF + (size_t)eb * HH + j) = hv;
                }
            }
            __threadfence();
            __syncthreads();

            if (tid == 0) {
                unsigned arr = atomicAdd(&g_cnt, 1u);
                if (arr == REC_CTAS - 1) {
                    atomicExch(&g_cnt, 0u);
                    __threadfence();
                    atomicAdd(&g_gen, 1u);
                } else if (t < TT - 1) {
                    while ((*(volatile unsigned*)&g_gen) - base < (unsigned)(t + 2))
                        __nanosleep(40);
                }
                __threadfence();
            }
            __syncthreads();
        }

        for (int i = tid; i < 512; i += 256)
            out[OUT_CELL_OFF + (size_t)(i >> 3) * HH + j0 + (i & 7)] = cellb[i];
        __syncthreads();

        // join the tile pool
        gemm_drain(hbase, gbar0, ps, base, tid, wid, lid, &s_q, bq, out);
    } else {
        // ================= gemm workers (CTAs 64..147) =================
        gemm_drain(hbase, gbar0, ps, base, tid, wid, lid, &s_q, bq, out);
    }
}

// ---------------- launch ----------------
extern "C" void kernel_launch(void* const* d_in, const int* in_sizes, int n_in,
                              void* d_out, int out_size) {
    const int*   x     = (const int*)  d_in[0];
    const float* state = (const float*)d_in[1];
    const float* cell  = (const float*)d_in[2];
    const float* W_xi  = (const float*)d_in[3];
    const float* W_hi  = (const float*)d_in[4];
    const float* b_i   = (const float*)d_in[5];
    const float* W_xf  = (const float*)d_in[6];
    const float* W_hf  = (const float*)d_in[7];
    const float* b_f   = (const float*)d_in[8];
    const float* W_xo  = (const float*)d_in[9];
    const float* W_ho  = (const float*)d_in[10];
    const float* b_o   = (const float*)d_in[11];
    const float* W_xc  = (const float*)d_in[12];
    const float* W_hc  = (const float*)d_in[13];
    const float* b_c   = (const float*)d_in[14];
    const float* W_hq  = (const float*)d_in[15];
    const float* b_q   = (const float*)d_in[16];
    float* out = (float*)d_out;

    cudaFuncSetAttribute(lstm_fused, cudaFuncAttributeMaxDynamicSharedMemorySize, SM_TOT);

    prep1<<<1024 + 32 * NTILES, 256>>>(W_hq, W_hi, W_hf, W_ho, W_hc);
    prep2<<<16384 + 16, 256>>>(x, state, W_xi, W_xf, W_xo, W_xc,
                               b_i, b_f, b_o, b_c);
    lstm_fused<<<ALL_CTAS, 256, SM_TOT>>>(cell, b_q, out);
}